// round 7
// baseline (speedup 1.0000x reference)
#include <cuda_runtime.h>
#include <cuda_bf16.h>
#include <cstdint>
#include <math.h>

#define BATCH 2
#define TSEQ  4096
#define NH    16
#define HD    64
#define CEMB  1024
#define MROWS (BATCH*TSEQ)          // 8192
#define SCALE 0.125f                // 1/sqrt(64)

// ---------------- scratch ------------------------------------------------------
__device__ __nv_bfloat16 g_xh[(size_t)MROWS*CEMB];
__device__ __nv_bfloat16 g_xl[(size_t)MROWS*CEMB];
__device__ __nv_bfloat16 g_yh[(size_t)MROWS*CEMB];
__device__ __nv_bfloat16 g_yl[(size_t)MROWS*CEMB];
__device__ __nv_bfloat16 g_wqh[(size_t)3*CEMB*CEMB];   // [N,K] K-major
__device__ __nv_bfloat16 g_wql[(size_t)3*CEMB*CEMB];
__device__ __nv_bfloat16 g_wph[(size_t)CEMB*CEMB];
__device__ __nv_bfloat16 g_wpl[(size_t)CEMB*CEMB];
__device__ __nv_bfloat16 g_qh[(size_t)BATCH*NH*TSEQ*HD];
__device__ __nv_bfloat16 g_ql[(size_t)BATCH*NH*TSEQ*HD];
__device__ __nv_bfloat16 g_kh[(size_t)BATCH*NH*TSEQ*HD];
__device__ __nv_bfloat16 g_kl[(size_t)BATCH*NH*TSEQ*HD];
__device__ __nv_bfloat16 g_vh[(size_t)BATCH*NH*TSEQ*HD];
__device__ __nv_bfloat16 g_vl[(size_t)BATCH*NH*TSEQ*HD];

// ---------------- PTX helpers --------------------------------------------------
__device__ __forceinline__ uint32_t smem_u32(const void* p) {
    uint32_t a;
    asm("{ .reg .u64 t; cvta.to.shared.u64 t, %1; cvt.u32.u64 %0, t; }"
        : "=r"(a) : "l"(p));
    return a;
}
__device__ __forceinline__ void cpasync16(uint32_t saddr, const void* g) {
    asm volatile("cp.async.cg.shared.global [%0], [%1], 16;"
                 :: "r"(saddr), "l"(g) : "memory");
}
#define CP_COMMIT() asm volatile("cp.async.commit_group;" ::: "memory")
#define CP_WAIT1()  asm volatile("cp.async.wait_group 1;" ::: "memory")
#define CP_WAIT0()  asm volatile("cp.async.wait_group 0;" ::: "memory")

__device__ __forceinline__ void ldmx4(uint32_t* r, uint32_t addr) {
    asm volatile("ldmatrix.sync.aligned.m8n8.x4.shared.b16 {%0,%1,%2,%3}, [%4];"
        : "=r"(r[0]), "=r"(r[1]), "=r"(r[2]), "=r"(r[3]) : "r"(addr));
}
__device__ __forceinline__ void ldmx2(uint32_t* r, uint32_t addr) {
    asm volatile("ldmatrix.sync.aligned.m8n8.x2.shared.b16 {%0,%1}, [%2];"
        : "=r"(r[0]), "=r"(r[1]) : "r"(addr));
}
__device__ __forceinline__ void ldmx4t(uint32_t* r, uint32_t addr) {
    asm volatile("ldmatrix.sync.aligned.m8n8.x4.trans.shared.b16 {%0,%1,%2,%3}, [%4];"
        : "=r"(r[0]), "=r"(r[1]), "=r"(r[2]), "=r"(r[3]) : "r"(addr));
}
__device__ __forceinline__ void mma16816(float* d, const uint32_t* a,
                                         const uint32_t* b) {
    asm volatile(
        "mma.sync.aligned.m16n8k16.row.col.f32.bf16.bf16.f32 "
        "{%0,%1,%2,%3}, {%4,%5,%6,%7}, {%8,%9}, {%0,%1,%2,%3};"
        : "+f"(d[0]), "+f"(d[1]), "+f"(d[2]), "+f"(d[3])
        : "r"(a[0]), "r"(a[1]), "r"(a[2]), "r"(a[3]), "r"(b[0]), "r"(b[1]));
}

__device__ __forceinline__ float2 bf2f(uint32_t u) {
    __nv_bfloat162 b = *(__nv_bfloat162*)&u;
    return __bfloat1622float2(b);
}
__device__ __forceinline__ uint32_t packbf(float x, float y) {
    __nv_bfloat162 t = __floats2bfloat162_rn(x, y);
    return *(uint32_t*)&t;
}
__device__ __forceinline__ void split1(float v, unsigned short& h, unsigned short& l) {
    __nv_bfloat16 hb = __float2bfloat16_rn(v);
    __nv_bfloat16 lb = __float2bfloat16_rn(v - __bfloat162float(hb));
    h = __bfloat16_as_ushort(hb);
    l = __bfloat16_as_ushort(lb);
}

// ---------------- conversion kernels -------------------------------------------
__global__ void conv_split_x(const float* __restrict__ src, int n) {
    int i = (blockIdx.x * 256 + threadIdx.x) * 4;
    if (i < n) {
        float4 v = *(const float4*)&src[i];
        ushort4 h, l;
        split1(v.x, h.x, l.x); split1(v.y, h.y, l.y);
        split1(v.z, h.z, l.z); split1(v.w, h.w, l.w);
        *(ushort4*)&g_xh[i] = h;
        *(ushort4*)&g_xl[i] = l;
    }
}
template <int W>
__global__ void conv_split_T(const float* __restrict__ w, int K, int N) {
    __shared__ float t[32][33];
    __nv_bfloat16* hiT = (W == 0) ? g_wqh : g_wph;
    __nv_bfloat16* loT = (W == 0) ? g_wql : g_wpl;
    int n0 = blockIdx.x * 32, k0 = blockIdx.y * 32;
    int tx = threadIdx.x & 31, ty = threadIdx.x >> 5;
    for (int r = ty; r < 32; r += 8)
        t[r][tx] = w[(size_t)(k0 + r) * N + n0 + tx];
    __syncthreads();
    for (int r = ty; r < 32; r += 8) {
        float v = t[tx][r];
        unsigned short h, l;
        split1(v, h, l);
        size_t o = (size_t)(n0 + r) * K + k0 + tx;
        hiT[o] = __ushort_as_bfloat16(h);
        loT[o] = __ushort_as_bfloat16(l);
    }
}

// ---------------- bf16x3 GEMM, product-major MMA ordering ----------------------
// CTA 128x128, BK=64, 256 thr (8 warps 2x4, warp 64x32), 2-stage cp.async.
#define BK    64
#define ROWB  144                   // 72 bf16 padded rows
#define MATB  (128*ROWB)            // 18432
#define STAGEB (4*MATB)             // 73728
#define GSMEM (2*STAGEB)            // 147456

template <int MODE>
__global__ __launch_bounds__(256, 1)
void gemm_mma(const float* __restrict__ bias, float* __restrict__ out)
{
    extern __shared__ __align__(16) char sm[];
    uint32_t smb = smem_u32(sm);

    const __nv_bfloat16* Ah = (MODE == 0) ? g_xh : g_yh;
    const __nv_bfloat16* Al = (MODE == 0) ? g_xl : g_yl;
    const __nv_bfloat16* Bh = (MODE == 0) ? g_wqh : g_wph;
    const __nv_bfloat16* Bl = (MODE == 0) ? g_wql : g_wpl;

    int tid = threadIdx.x;
    int wid = tid >> 5, lane = tid & 31;
    int wm = wid >> 2, wn = wid & 3;
    int mBase = blockIdx.y * 128, nBase = blockIdx.x * 128;

    float acc[4][4][4];
#pragma unroll
    for (int mi = 0; mi < 4; mi++)
#pragma unroll
        for (int ni = 0; ni < 4; ni++)
#pragma unroll
            for (int q = 0; q < 4; q++) acc[mi][ni][q] = 0.f;

    const __nv_bfloat16* mats[4] = { Ah, Al, Bh, Bl };

    auto load_stage = [&](int st, int kt) {
        int k0 = kt * BK;
#pragma unroll
        for (int m = 0; m < 4; m++) {
            const __nv_bfloat16* src = mats[m];
            int rbase = (m < 2) ? mBase : nBase;
            uint32_t sb = smb + st * STAGEB + m * MATB;
#pragma unroll
            for (int c = tid; c < 1024; c += 256) {
                int row = c >> 3, ch = c & 7;
                cpasync16(sb + row * ROWB + ch * 16,
                          src + (size_t)(rbase + row) * CEMB + k0 + ch * 8);
            }
        }
    };

    int g = lane >> 3, w = lane & 7;
    uint32_t a_row = (wm * 64 + ((g & 1) << 3) + w) * ROWB;
    uint32_t b_row = (wn * 32 + w) * ROWB;
    uint32_t ka_off = ((g >> 1) << 3) * 2;
    uint32_t kb_off = ((g & 1) << 3) * 2;

    load_stage(0, 0); CP_COMMIT();

    for (int kt = 0; kt < 16; kt++) {
        CP_WAIT0();
        __syncthreads();
        if (kt + 1 < 16) { load_stage((kt + 1) & 1, kt + 1); CP_COMMIT(); }

        int s = kt & 1;
        uint32_t bAh = smb + s * STAGEB;
        uint32_t bAl = bAh + MATB;
        uint32_t bBh = bAl + MATB;
        uint32_t bBl = bBh + MATB;

#pragma unroll
        for (int ks = 0; ks < 4; ks++) {
            uint32_t ka = ks * 32 + ka_off;
            uint32_t kb = ks * 32 + kb_off;
            uint32_t ah[4][4], al[4][4], bh[4][2], bl[4][2];
#pragma unroll
            for (int mi = 0; mi < 4; mi++) {
                uint32_t ro = a_row + mi * 16 * ROWB;
                ldmx4(ah[mi], bAh + ro + ka);
                ldmx4(al[mi], bAl + ro + ka);
            }
#pragma unroll
            for (int ni = 0; ni < 4; ni++) {
                uint32_t ro = b_row + ni * 8 * ROWB;
                ldmx2(bh[ni], bBh + ro + kb);
                ldmx2(bl[ni], bBl + ro + kb);
            }
            // product-major: each acc touched once per 16-MMA pass
#pragma unroll
            for (int mi = 0; mi < 4; mi++)
#pragma unroll
                for (int ni = 0; ni < 4; ni++)
                    mma16816(acc[mi][ni], ah[mi], bh[ni]);
#pragma unroll
            for (int mi = 0; mi < 4; mi++)
#pragma unroll
                for (int ni = 0; ni < 4; ni++)
                    mma16816(acc[mi][ni], ah[mi], bl[ni]);
#pragma unroll
            for (int mi = 0; mi < 4; mi++)
#pragma unroll
                for (int ni = 0; ni < 4; ni++)
                    mma16816(acc[mi][ni], al[mi], bh[ni]);
        }
        __syncthreads();
    }

    // epilogue
    int r_in = lane >> 2, c_in = (lane & 3) * 2;
#pragma unroll
    for (int mi = 0; mi < 4; mi++) {
#pragma unroll
        for (int half = 0; half < 2; half++) {
            int m = mBase + wm * 64 + mi * 16 + r_in + half * 8;
#pragma unroll
            for (int ni = 0; ni < 4; ni++) {
                int n = nBase + wn * 32 + ni * 8 + c_in;
                float v0 = acc[mi][ni][half * 2 + 0] + bias[n];
                float v1 = acc[mi][ni][half * 2 + 1] + bias[n + 1];
                if (MODE == 0) {
                    int b = m >> 12, t = m & 4095;
                    int sect = n >> 10, cc = n & 1023;
                    int head = cc >> 6, d0 = cc & 63;
                    unsigned short h0, l0, h1, l1;
                    split1(v0, h0, l0); split1(v1, h1, l1);
                    uint32_t hv = (uint32_t)h0 | ((uint32_t)h1 << 16);
                    uint32_t lv = (uint32_t)l0 | ((uint32_t)l1 << 16);
                    size_t off = (((size_t)(b * NH + head)) * TSEQ + t) * HD + d0;
                    __nv_bfloat16* dh = (sect == 0) ? g_qh : (sect == 1) ? g_kh : g_vh;
                    __nv_bfloat16* dl = (sect == 0) ? g_ql : (sect == 1) ? g_kl : g_vl;
                    *(uint32_t*)&dh[off] = hv;
                    *(uint32_t*)&dl[off] = lv;
                } else {
                    *(float2*)&out[(size_t)m * CEMB + n] = make_float2(v0, v1);
                }
            }
        }
    }
}

// ---------------- HMMA block-sparse flash attention (512 thr, col-split) ------
#define SMQ_H  0
#define SMQ_L  18432
#define SMKV   36864
#define STAGEKV 73728
#define SST_OFF (SMKV + 2*STAGEKV)          // 184320
#define ATTN_SMEM2 (SST_OFF + 128*33*4)     // 201216
#define MERGE_B 4352

template <int NNI>
__device__ __forceinline__ void dense_block(
    uint32_t smb, uint32_t kst, int lane, int rg, int colbase, int i0, int jb,
    float (&oacc)[8][4], float (&m)[2], float (&l)[2])
{
    const int NKK = NNI / 2;
    const int GRP = (NNI >= 4) ? 4 : NNI;
    int g = lane >> 3, w = lane & 7;
    uint32_t arow = smb + SMQ_H + (rg * 16 + ((g & 1) << 3) + w) * 144;
    uint32_t ka = (g >> 1) * 16;
    uint32_t kboff = (g & 1) * 16;

    float sacc[NNI][4];
#pragma unroll
    for (int ni = 0; ni < NNI; ni++)
#pragma unroll
        for (int q = 0; q < 4; q++) sacc[ni][q] = 0.f;

#pragma unroll
    for (int ks = 0; ks < 4; ks++) {
        uint32_t qh4[4], ql4[4];
        ldmx4(qh4, arow + ks * 32 + ka);
        ldmx4(ql4, arow + 18432 + ks * 32 + ka);
#pragma unroll
        for (int grp = 0; grp < NNI / GRP; grp++) {
            uint32_t bh2[GRP][2], bl2[GRP][2];
#pragma unroll
            for (int u = 0; u < GRP; u++) {
                int ni = grp * GRP + u;
                uint32_t brow = kst + (colbase + ni * 8 + w) * 144 + kboff + ks * 32;
                ldmx2(bh2[u], brow);
                ldmx2(bl2[u], brow + 18432);
            }
#pragma unroll
            for (int u = 0; u < GRP; u++)
                mma16816(sacc[grp * GRP + u], qh4, bh2[u]);
#pragma unroll
            for (int u = 0; u < GRP; u++)
                mma16816(sacc[grp * GRP + u], qh4, bl2[u]);
#pragma unroll
            for (int u = 0; u < GRP; u++)
                mma16816(sacc[grp * GRP + u], ql4, bh2[u]);
        }
    }

    int c0 = (lane & 3) * 2;
    float mb0 = -1e30f, mb1 = -1e30f;
#pragma unroll
    for (int ni = 0; ni < NNI; ni++) {
        int jB = jb + ni * 8 + c0;
#pragma unroll
        for (int q = 0; q < 4; q++) {
            int jj = jB + (q & 1);
            int ii = (q < 2) ? i0 : i0 + 8;
            int diff = ii - jj;
            bool ok = diff >= 0 &&
                      (diff < 256 || (diff & 127) == 0 || jj < 16);
            sacc[ni][q] = ok ? sacc[ni][q] * SCALE : -1e30f;
        }
        mb0 = fmaxf(mb0, fmaxf(sacc[ni][0], sacc[ni][1]));
        mb1 = fmaxf(mb1, fmaxf(sacc[ni][2], sacc[ni][3]));
    }
    mb0 = fmaxf(mb0, __shfl_xor_sync(0xffffffffu, mb0, 1));
    mb0 = fmaxf(mb0, __shfl_xor_sync(0xffffffffu, mb0, 2));
    mb1 = fmaxf(mb1, __shfl_xor_sync(0xffffffffu, mb1, 1));
    mb1 = fmaxf(mb1, __shfl_xor_sync(0xffffffffu, mb1, 2));

    float mn0 = fmaxf(fmaxf(m[0], mb0), -1e28f);
    float mn1 = fmaxf(fmaxf(m[1], mb1), -1e28f);
    float cs0 = __expf(m[0] - mn0), cs1 = __expf(m[1] - mn1);
    float ls0 = 0.f, ls1 = 0.f;
#pragma unroll
    for (int ni = 0; ni < NNI; ni++) {
        float p0 = __expf(sacc[ni][0] - mn0);
        float p1 = __expf(sacc[ni][1] - mn0);
        float p2 = __expf(sacc[ni][2] - mn1);
        float p3 = __expf(sacc[ni][3] - mn1);
        sacc[ni][0] = p0; sacc[ni][1] = p1; sacc[ni][2] = p2; sacc[ni][3] = p3;
        ls0 += p0 + p1; ls1 += p2 + p3;
    }
    ls0 += __shfl_xor_sync(0xffffffffu, ls0, 1);
    ls0 += __shfl_xor_sync(0xffffffffu, ls0, 2);
    ls1 += __shfl_xor_sync(0xffffffffu, ls1, 1);
    ls1 += __shfl_xor_sync(0xffffffffu, ls1, 2);
    l[0] = l[0] * cs0 + ls0; m[0] = mn0;
    l[1] = l[1] * cs1 + ls1; m[1] = mn1;
#pragma unroll
    for (int nd = 0; nd < 8; nd++) {
        oacc[nd][0] *= cs0; oacc[nd][1] *= cs0;
        oacc[nd][2] *= cs1; oacc[nd][3] *= cs1;
    }

    uint32_t vbase = kst + 2 * 18432;
    int jrow = ((g & 1) << 3) + w;
    int dcol = (g >> 1) * 16;
#pragma unroll
    for (int kk = 0; kk < NKK; kk++) {
        float* s0 = sacc[2 * kk];
        float* s1 = sacc[2 * kk + 1];
        float h00 = __bfloat162float(__float2bfloat16_rn(s0[0]));
        float h01 = __bfloat162float(__float2bfloat16_rn(s0[1]));
        float h02 = __bfloat162float(__float2bfloat16_rn(s0[2]));
        float h03 = __bfloat162float(__float2bfloat16_rn(s0[3]));
        float h10 = __bfloat162float(__float2bfloat16_rn(s1[0]));
        float h11 = __bfloat162float(__float2bfloat16_rn(s1[1]));
        float h12 = __bfloat162float(__float2bfloat16_rn(s1[2]));
        float h13 = __bfloat162float(__float2bfloat16_rn(s1[3]));
        uint32_t pah[4], pal[4];
        pah[0] = packbf(h00, h01); pah[1] = packbf(h02, h03);
        pah[2] = packbf(h10, h11); pah[3] = packbf(h12, h13);
        pal[0] = packbf(s0[0] - h00, s0[1] - h01);
        pal[1] = packbf(s0[2] - h02, s0[3] - h03);
        pal[2] = packbf(s1[0] - h10, s1[1] - h11);
        pal[3] = packbf(s1[2] - h12, s1[3] - h13);
        // groups of 2 nd2: load V frags, then product-major passes
#pragma unroll
        for (int gv = 0; gv < 2; gv++) {
            uint32_t vh4[2][4], vl4[2][4];
#pragma unroll
            for (int u = 0; u < 2; u++) {
                int nd2 = gv * 2 + u;
                uint32_t addr = vbase + (colbase + kk * 16 + jrow) * 144 + nd2 * 32 + dcol;
                ldmx4t(vh4[u], addr);
                ldmx4t(vl4[u], addr + 18432);
            }
#pragma unroll
            for (int u = 0; u < 2; u++) {
                int nd2 = gv * 2 + u;
                mma16816(oacc[nd2 * 2],     pah, vh4[u]);
                mma16816(oacc[nd2 * 2 + 1], pah, vh4[u] + 2);
            }
#pragma unroll
            for (int u = 0; u < 2; u++) {
                int nd2 = gv * 2 + u;
                mma16816(oacc[nd2 * 2],     pah, vl4[u]);
                mma16816(oacc[nd2 * 2 + 1], pah, vl4[u] + 2);
            }
#pragma unroll
            for (int u = 0; u < 2; u++) {
                int nd2 = gv * 2 + u;
                mma16816(oacc[nd2 * 2],     pal, vh4[u]);
                mma16816(oacc[nd2 * 2 + 1], pal, vh4[u] + 2);
            }
        }
    }
}

__global__ __launch_bounds__(512, 1)
void attn_mma()
{
    extern __shared__ __align__(16) char sm[];
    uint32_t smb = smem_u32(sm);
    int tid = threadIdx.x, lane = tid & 31, wid = tid >> 5;
    int rg = wid >> 1, ch2 = wid & 1;
    int qb = blockIdx.x, bh = blockIdx.y;

    size_t qoff = ((size_t)bh * TSEQ + (size_t)qb * 128) * HD;
    for (int c = tid; c < 1024; c += 512) {
        int row = c >> 3, ch = c & 7;
        *(uint4*)(sm + SMQ_H + row * 144 + ch * 16) =
            *(const uint4*)&g_qh[qoff + row * HD + ch * 8];
        *(uint4*)(sm + SMQ_L + row * 144 + ch * 16) =
            *(const uint4*)&g_ql[qoff + row * HD + ch * 8];
    }

    float oacc[8][4];
#pragma unroll
    for (int nd = 0; nd < 8; nd++)
#pragma unroll
        for (int q = 0; q < 4; q++) oacc[nd][q] = 0.f;
    float m[2] = { -1e30f, -1e30f }, l[2] = { 0.f, 0.f };

    int kb_lo = (qb - 2 > 0) ? qb - 2 : 0;
    int blocks[4], bcols[4], ndense = 0;
    for (int kb = kb_lo; kb <= qb; kb++) { blocks[ndense] = kb; bcols[ndense] = 128; ndense++; }
    if (kb_lo > 0) { blocks[ndense] = 0; bcols[ndense] = 16; ndense++; }

    auto stage_kv = [&](int st, int idx) {
        int kb = blocks[idx];
        int nr = (bcols[idx] == 128) ? 128 : 16;
        uint32_t base = smb + SMKV + st * STAGEKV;
        const __nv_bfloat16* srcs[4] = { g_kh, g_kl, g_vh, g_vl };
#pragma unroll
        for (int mm = 0; mm < 4; mm++) {
            const __nv_bfloat16* src =
                srcs[mm] + ((size_t)bh * TSEQ + (size_t)kb * 128) * HD;
            for (int c = tid; c < nr * 8; c += 512) {
                int row = c >> 3, ch = c & 7;
                cpasync16(base + mm * 18432 + row * 144 + ch * 16,
                          src + row * HD + ch * 8);
            }
        }
    };

    stage_kv(0, 0); CP_COMMIT();
    int i0 = qb * 128 + rg * 16 + (lane >> 2);

    for (int it = 0; it < ndense; it++) {
        __syncthreads();
        if (it + 1 < ndense) { stage_kv((it + 1) & 1, it + 1); CP_COMMIT(); CP_WAIT1(); }
        else CP_WAIT0();
        __syncthreads();
        uint32_t kst = smb + SMKV + (it & 1) * STAGEKV;
        if (bcols[it] == 128)
            dense_block<8>(smb, kst, lane, rg, ch2 * 64, i0,
                           blocks[it] * 128 + ch2 * 64, oacc, m, l);
        else if (ch2 == 0)
            dense_block<2>(smb, kst, lane, rg, 0, i0, 0, oacc, m, l);
    }

    // strided diagonals: warp pair splits kb even/odd
    int nkb = qb - 2;
    float* Sst = (float*)(sm + SST_OFF);
    if (nkb > 0) {
        int part = lane & 3;
        for (int pass = 0; pass < 2; pass++) {
            int rloc = rg * 16 + pass * 8 + (lane >> 2);
            for (int kb = ch2; kb < nkb; kb += 2) {
                float sc;
                if (kb == 0 && rloc < 16) {
                    sc = -1e30f;
                } else {
                    int j = kb * 128 + rloc;
                    size_t kbase = ((size_t)bh * TSEQ + j) * HD + part * 16;
                    uint32_t qb0 = smb + SMQ_H + rloc * 144 + part * 32;
                    float sum = 0.f;
#pragma unroll
                    for (int seg = 0; seg < 2; seg++) {
                        uint32_t qh4[4], ql4[4];
                        asm volatile("ld.shared.v4.b32 {%0,%1,%2,%3}, [%4];"
                            : "=r"(qh4[0]), "=r"(qh4[1]), "=r"(qh4[2]), "=r"(qh4[3])
                            : "r"(qb0 + seg * 16));
                        asm volatile("ld.shared.v4.b32 {%0,%1,%2,%3}, [%4];"
                            : "=r"(ql4[0]), "=r"(ql4[1]), "=r"(ql4[2]), "=r"(ql4[3])
                            : "r"(qb0 + 18432 + seg * 16));
                        uint4 kh4 = *(const uint4*)&g_kh[kbase + seg * 8];
                        uint4 kl4 = *(const uint4*)&g_kl[kbase + seg * 8];
                        const uint32_t* khp = (const uint32_t*)&kh4;
                        const uint32_t* klp = (const uint32_t*)&kl4;
#pragma unroll
                        for (int u = 0; u < 4; u++) {
                            float2 qh2 = bf2f(qh4[u]), ql2 = bf2f(ql4[u]);
                            float2 kh2 = bf2f(khp[u]), kl2 = bf2f(klp[u]);
                            sum += (qh2.x + ql2.x) * (kh2.x + kl2.x);
                            sum += (qh2.y + ql2.y) * (kh2.y + kl2.y);
                        }
                    }
                    sum += __shfl_xor_sync(0xffffffffu, sum, 1);
                    sum += __shfl_xor_sync(0xffffffffu, sum, 2);
                    sc = sum * SCALE;
                }
                if (part == 0) Sst[rloc * 33 + kb] = sc;
            }
        }
        __syncwarp();

#pragma unroll
        for (int h = 0; h < 2; h++) {
            int r = rg * 16 + (lane >> 2) + h * 8;
            float mo = m[h], mx = mo;
            for (int kb = ch2; kb < nkb; kb += 2)
                mx = fmaxf(mx, Sst[r * 33 + kb]);
            mx = fmaxf(mx, -1e28f);
            float cs = __expf(mo - mx);
            float ls = 0.f;
#pragma unroll
            for (int nd = 0; nd < 8; nd++) {
                oacc[nd][h * 2 + 0] *= cs;
                oacc[nd][h * 2 + 1] *= cs;
            }
            for (int kb = ch2; kb < nkb; kb += 2) {
                float p = __expf(Sst[r * 33 + kb] - mx);
                ls += p;
                if (p > 0.f) {
                    int j = kb * 128 + r;
                    size_t vb = ((size_t)bh * TSEQ + j) * HD;
#pragma unroll
                    for (int nd = 0; nd < 8; nd++) {
                        int d0 = nd * 8 + (lane & 3) * 2;
                        float2 vh = bf2f(*(const uint32_t*)&g_vh[vb + d0]);
                        float2 vl = bf2f(*(const uint32_t*)&g_vl[vb + d0]);
                        oacc[nd][h * 2 + 0] += p * (vh.x + vl.x);
                        oacc[nd][h * 2 + 1] += p * (vh.y + vl.y);
                    }
                }
            }
            m[h] = mx;
            l[h] = l[h] * cs + ls;
        }
    }

    // pairwise split-softmax merge, then epilogue
    __syncthreads();
    {
        char* mb = sm + SMKV + wid * MERGE_B;
#pragma unroll
        for (int h = 0; h < 2; h++) {
            int row = (lane >> 2) + h * 8;
#pragma unroll
            for (int nd = 0; nd < 8; nd++) {
                int col = nd * 8 + (lane & 3) * 2;
                *(float2*)(mb + (row * 64 + col) * 4) =
                    make_float2(oacc[nd][h * 2], oacc[nd][h * 2 + 1]);
            }
            if ((lane & 3) == 0)
                *(float2*)(mb + 4096 + row * 8) = make_float2(m[h], l[h]);
        }
    }
    __syncthreads();
    if (ch2 == 0) {
        char* pb = sm + SMKV + (wid + 1) * MERGE_B;
        int b = bh >> 4, head = bh & 15;
#pragma unroll
        for (int h = 0; h < 2; h++) {
            int row = (lane >> 2) + h * 8;
            float2 ml = *(float2*)(pb + 4096 + row * 8);
            float mx = fmaxf(m[h], ml.x);
            float f0 = __expf(m[h] - mx), f1 = __expf(ml.x - mx);
            float L = l[h] * f0 + ml.y * f1;
            float inv = 1.f / L;
            int i = qb * 128 + rg * 16 + row;
            size_t row_off = ((size_t)(b * TSEQ + i)) * CEMB + head * HD;
#pragma unroll
            for (int nd = 0; nd < 8; nd++) {
                int col = nd * 8 + (lane & 3) * 2;
                float2 o1 = *(float2*)(pb + (row * 64 + col) * 4);
                float y0 = (oacc[nd][h * 2 + 0] * f0 + o1.x * f1) * inv;
                float y1 = (oacc[nd][h * 2 + 1] * f0 + o1.y * f1) * inv;
                unsigned short h0, l0, h1, l1;
                split1(y0, h0, l0); split1(y1, h1, l1);
                *(uint32_t*)&g_yh[row_off + col] = (uint32_t)h0 | ((uint32_t)h1 << 16);
                *(uint32_t*)&g_yl[row_off + col] = (uint32_t)l0 | ((uint32_t)l1 << 16);
            }
        }
    }
}

// ---------------- launch -------------------------------------------------------
extern "C" void kernel_launch(void* const* d_in, const int* in_sizes, int n_in,
                              void* d_out, int out_size)
{
    const float* x      = (const float*)d_in[0];
    const float* w_qkv  = (const float*)d_in[1];
    const float* b_qkv  = (const float*)d_in[2];
    const float* w_proj = (const float*)d_in[3];
    const float* b_proj = (const float*)d_in[4];
    float* out = (float*)d_out;

    cudaFuncSetAttribute(gemm_mma<0>,
                         cudaFuncAttributeMaxDynamicSharedMemorySize, GSMEM);
    cudaFuncSetAttribute(gemm_mma<1>,
                         cudaFuncAttributeMaxDynamicSharedMemorySize, GSMEM);
    cudaFuncSetAttribute(attn_mma,
                         cudaFuncAttributeMaxDynamicSharedMemorySize, ATTN_SMEM2);

    int n_x = MROWS * CEMB;
    conv_split_x<<<n_x / 4 / 256, 256>>>(x, n_x);
    conv_split_T<0><<<dim3(3 * CEMB / 32, CEMB / 32), 256>>>(w_qkv, CEMB, 3 * CEMB);
    conv_split_T<1><<<dim3(CEMB / 32, CEMB / 32), 256>>>(w_proj, CEMB, CEMB);

    // 1) QKV GEMM -> Q/K/V bf16 hi/lo
    gemm_mma<0><<<dim3(3 * CEMB / 128, MROWS / 128), 256, GSMEM>>>(b_qkv, nullptr);

    // 2) HMMA block-sparse flash attention -> yh/yl
    attn_mma<<<dim3(TSEQ / 128, BATCH * NH), 512, ATTN_SMEM2>>>();

    // 3) output projection -> out
    gemm_mma<1><<<dim3(CEMB / 128, MROWS / 128), 256, GSMEM>>>(b_proj, out);
}

// round 8
// speedup vs baseline: 2.2222x; 2.2222x over previous
#include <cuda_runtime.h>
#include <cuda_fp16.h>
#include <cstdint>
#include <math.h>

#define BATCH 2
#define TSEQ  4096
#define NH    16
#define HD    64
#define CEMB  1024
#define MROWS (BATCH*TSEQ)          // 8192
#define SCALE 0.125f                // 1/sqrt(64)

// ---------------- scratch (fp16 single precision operands) --------------------
__device__ __half g_x16[(size_t)MROWS*CEMB];
__device__ __half g_y16[(size_t)MROWS*CEMB];
__device__ __half g_wq16[(size_t)3*CEMB*CEMB];   // [N,K] K-major
__device__ __half g_wp16[(size_t)CEMB*CEMB];
__device__ __half g_q16[(size_t)BATCH*NH*TSEQ*HD];
__device__ __half g_k16[(size_t)BATCH*NH*TSEQ*HD];
__device__ __half g_v16[(size_t)BATCH*NH*TSEQ*HD];

// ---------------- PTX helpers --------------------------------------------------
__device__ __forceinline__ uint32_t smem_u32(const void* p) {
    uint32_t a;
    asm("{ .reg .u64 t; cvta.to.shared.u64 t, %1; cvt.u32.u64 %0, t; }"
        : "=r"(a) : "l"(p));
    return a;
}
__device__ __forceinline__ void cpasync16(uint32_t saddr, const void* g) {
    asm volatile("cp.async.cg.shared.global [%0], [%1], 16;"
                 :: "r"(saddr), "l"(g) : "memory");
}
#define CP_COMMIT() asm volatile("cp.async.commit_group;" ::: "memory")
#define CP_WAIT1()  asm volatile("cp.async.wait_group 1;" ::: "memory")
#define CP_WAIT0()  asm volatile("cp.async.wait_group 0;" ::: "memory")

__device__ __forceinline__ void ldmx4(uint32_t* r, uint32_t addr) {
    asm volatile("ldmatrix.sync.aligned.m8n8.x4.shared.b16 {%0,%1,%2,%3}, [%4];"
        : "=r"(r[0]), "=r"(r[1]), "=r"(r[2]), "=r"(r[3]) : "r"(addr));
}
__device__ __forceinline__ void ldmx2(uint32_t* r, uint32_t addr) {
    asm volatile("ldmatrix.sync.aligned.m8n8.x2.shared.b16 {%0,%1}, [%2];"
        : "=r"(r[0]), "=r"(r[1]) : "r"(addr));
}
__device__ __forceinline__ void ldmx4t(uint32_t* r, uint32_t addr) {
    asm volatile("ldmatrix.sync.aligned.m8n8.x4.trans.shared.b16 {%0,%1,%2,%3}, [%4];"
        : "=r"(r[0]), "=r"(r[1]), "=r"(r[2]), "=r"(r[3]) : "r"(addr));
}
__device__ __forceinline__ void mma16816(float* d, const uint32_t* a,
                                         const uint32_t* b) {
    asm volatile(
        "mma.sync.aligned.m16n8k16.row.col.f32.f16.f16.f32 "
        "{%0,%1,%2,%3}, {%4,%5,%6,%7}, {%8,%9}, {%0,%1,%2,%3};"
        : "+f"(d[0]), "+f"(d[1]), "+f"(d[2]), "+f"(d[3])
        : "r"(a[0]), "r"(a[1]), "r"(a[2]), "r"(a[3]), "r"(b[0]), "r"(b[1]));
}

__device__ __forceinline__ float2 h2f2(uint32_t u) {
    __half2 h = *(__half2*)&u;
    return __half22float2(h);
}
__device__ __forceinline__ uint32_t packh(float x, float y) {
    __half2 t = __floats2half2_rn(x, y);
    return *(uint32_t*)&t;
}

// ---------------- conversion kernels -------------------------------------------
__global__ void conv_f16_x(const float* __restrict__ src, int n) {
    int i = (blockIdx.x * 256 + threadIdx.x) * 4;
    if (i < n) {
        float4 v = *(const float4*)&src[i];
        uint2 p;
        p.x = packh(v.x, v.y);
        p.y = packh(v.z, v.w);
        *(uint2*)&g_x16[i] = p;
    }
}
template <int W>
__global__ void conv_f16_T(const float* __restrict__ w, int K, int N) {
    __shared__ float t[32][33];
    __half* dT = (W == 0) ? g_wq16 : g_wp16;
    int n0 = blockIdx.x * 32, k0 = blockIdx.y * 32;
    int tx = threadIdx.x & 31, ty = threadIdx.x >> 5;
    for (int r = ty; r < 32; r += 8)
        t[r][tx] = w[(size_t)(k0 + r) * N + n0 + tx];
    __syncthreads();
    for (int r = ty; r < 32; r += 8) {
        float v = t[tx][r];
        dT[(size_t)(n0 + r) * K + k0 + tx] = __float2half_rn(v);
    }
}

// ---------------- fp16 GEMM on mma.sync ----------------------------------------
// CTA 128x128, BK=64, 256 thr (8 warps 2x4, warp 64x32), 2-stage cp.async.
#define BK    64
#define ROWB  144                   // 64 halfs padded to 144 B
#define MATB  (128*ROWB)            // 18432
#define STAGEB (2*MATB)             // 36864 (A + B)
#define GSMEM (2*STAGEB)            // 73728 -> 2 CTAs/SM

template <int MODE>
__global__ __launch_bounds__(256, 2)
void gemm_mma(const float* __restrict__ bias, float* __restrict__ out)
{
    extern __shared__ __align__(16) char sm[];
    uint32_t smb = smem_u32(sm);

    const __half* A16 = (MODE == 0) ? g_x16 : g_y16;
    const __half* B16 = (MODE == 0) ? g_wq16 : g_wp16;

    int tid = threadIdx.x;
    int wid = tid >> 5, lane = tid & 31;
    int wm = wid >> 2, wn = wid & 3;
    int mBase = blockIdx.y * 128, nBase = blockIdx.x * 128;

    float acc[4][4][4];
#pragma unroll
    for (int mi = 0; mi < 4; mi++)
#pragma unroll
        for (int ni = 0; ni < 4; ni++)
#pragma unroll
            for (int q = 0; q < 4; q++) acc[mi][ni][q] = 0.f;

    auto load_stage = [&](int st, int kt) {
        int k0 = kt * BK;
        uint32_t sb = smb + st * STAGEB;
#pragma unroll
        for (int c = tid; c < 1024; c += 256) {
            int row = c >> 3, ch = c & 7;
            cpasync16(sb + row * ROWB + ch * 16,
                      A16 + (size_t)(mBase + row) * CEMB + k0 + ch * 8);
        }
#pragma unroll
        for (int c = tid; c < 1024; c += 256) {
            int row = c >> 3, ch = c & 7;
            cpasync16(sb + MATB + row * ROWB + ch * 16,
                      B16 + (size_t)(nBase + row) * CEMB + k0 + ch * 8);
        }
    };

    int g = lane >> 3, w = lane & 7;
    uint32_t a_row = (wm * 64 + ((g & 1) << 3) + w) * ROWB;
    uint32_t b_row = (wn * 32 + w) * ROWB;
    uint32_t ka_off = ((g >> 1) << 3) * 2;
    uint32_t kb_off = ((g & 1) << 3) * 2;

    load_stage(0, 0); CP_COMMIT();

    for (int kt = 0; kt < 16; kt++) {
        CP_WAIT0();
        __syncthreads();
        if (kt + 1 < 16) { load_stage((kt + 1) & 1, kt + 1); CP_COMMIT(); }

        int s = kt & 1;
        uint32_t bA = smb + s * STAGEB;
        uint32_t bB = bA + MATB;

#pragma unroll
        for (int ks = 0; ks < 4; ks++) {
            uint32_t ka = ks * 32 + ka_off;
            uint32_t kb = ks * 32 + kb_off;
            uint32_t ah[4][4], bh[4][2];
#pragma unroll
            for (int mi = 0; mi < 4; mi++)
                ldmx4(ah[mi], bA + a_row + mi * 16 * ROWB + ka);
#pragma unroll
            for (int ni = 0; ni < 4; ni++)
                ldmx2(bh[ni], bB + b_row + ni * 8 * ROWB + kb);
#pragma unroll
            for (int mi = 0; mi < 4; mi++)
#pragma unroll
                for (int ni = 0; ni < 4; ni++)
                    mma16816(acc[mi][ni], ah[mi], bh[ni]);
        }
        __syncthreads();
    }

    // epilogue
    int r_in = lane >> 2, c_in = (lane & 3) * 2;
#pragma unroll
    for (int mi = 0; mi < 4; mi++) {
#pragma unroll
        for (int half = 0; half < 2; half++) {
            int m = mBase + wm * 64 + mi * 16 + r_in + half * 8;
#pragma unroll
            for (int ni = 0; ni < 4; ni++) {
                int n = nBase + wn * 32 + ni * 8 + c_in;
                float v0 = acc[mi][ni][half * 2 + 0] + bias[n];
                float v1 = acc[mi][ni][half * 2 + 1] + bias[n + 1];
                if (MODE == 0) {
                    int b = m >> 12, t = m & 4095;
                    int sect = n >> 10, cc = n & 1023;
                    int head = cc >> 6, d0 = cc & 63;
                    size_t off = (((size_t)(b * NH + head)) * TSEQ + t) * HD + d0;
                    __half* dst = (sect == 0) ? g_q16 : (sect == 1) ? g_k16 : g_v16;
                    *(uint32_t*)&dst[off] = packh(v0, v1);
                } else {
                    *(float2*)&out[(size_t)m * CEMB + n] = make_float2(v0, v1);
                }
            }
        }
    }
}

// ---------------- fp16 HMMA block-sparse flash attention -----------------------
// 512 thr = 16 warps: 8 row-groups x 2 col-halves of 64 key-cols.
#define SMQ    0
#define SMKV   18432
#define STAGEKV 36864                       // K(18432)+V(18432)
#define SST_OFF (SMKV + 2*STAGEKV)          // 92160
#define ATTN_SMEM2 (SST_OFF + 128*33*4)     // 109056
#define MERGE_B 4352

template <int NNI>
__device__ __forceinline__ void dense_block(
    uint32_t smb, uint32_t kst, int lane, int rg, int colbase, int i0, int jb,
    float (&oacc)[8][4], float (&m)[2], float (&l)[2])
{
    const int NKK = NNI / 2;
    const int GRP = (NNI >= 4) ? 4 : NNI;
    int g = lane >> 3, w = lane & 7;
    uint32_t arow = smb + SMQ + (rg * 16 + ((g & 1) << 3) + w) * 144;
    uint32_t ka = (g >> 1) * 16;
    uint32_t kboff = (g & 1) * 16;

    float sacc[NNI][4];
#pragma unroll
    for (int ni = 0; ni < NNI; ni++)
#pragma unroll
        for (int q = 0; q < 4; q++) sacc[ni][q] = 0.f;

#pragma unroll
    for (int ks = 0; ks < 4; ks++) {
        uint32_t q4[4];
        ldmx4(q4, arow + ks * 32 + ka);
#pragma unroll
        for (int grp = 0; grp < NNI / GRP; grp++) {
            uint32_t kb2[GRP][2];
#pragma unroll
            for (int u = 0; u < GRP; u++) {
                int ni = grp * GRP + u;
                ldmx2(kb2[u], kst + (colbase + ni * 8 + w) * 144 + kboff + ks * 32);
            }
#pragma unroll
            for (int u = 0; u < GRP; u++)
                mma16816(sacc[grp * GRP + u], q4, kb2[u]);
        }
    }

    int c0 = (lane & 3) * 2;
    float mb0 = -1e30f, mb1 = -1e30f;
#pragma unroll
    for (int ni = 0; ni < NNI; ni++) {
        int jB = jb + ni * 8 + c0;
#pragma unroll
        for (int q = 0; q < 4; q++) {
            int jj = jB + (q & 1);
            int ii = (q < 2) ? i0 : i0 + 8;
            int diff = ii - jj;
            bool ok = diff >= 0 &&
                      (diff < 256 || (diff & 127) == 0 || jj < 16);
            sacc[ni][q] = ok ? sacc[ni][q] * SCALE : -1e30f;
        }
        mb0 = fmaxf(mb0, fmaxf(sacc[ni][0], sacc[ni][1]));
        mb1 = fmaxf(mb1, fmaxf(sacc[ni][2], sacc[ni][3]));
    }
    mb0 = fmaxf(mb0, __shfl_xor_sync(0xffffffffu, mb0, 1));
    mb0 = fmaxf(mb0, __shfl_xor_sync(0xffffffffu, mb0, 2));
    mb1 = fmaxf(mb1, __shfl_xor_sync(0xffffffffu, mb1, 1));
    mb1 = fmaxf(mb1, __shfl_xor_sync(0xffffffffu, mb1, 2));

    float mn0 = fmaxf(fmaxf(m[0], mb0), -1e28f);
    float mn1 = fmaxf(fmaxf(m[1], mb1), -1e28f);
    float cs0 = __expf(m[0] - mn0), cs1 = __expf(m[1] - mn1);
    float ls0 = 0.f, ls1 = 0.f;
#pragma unroll
    for (int ni = 0; ni < NNI; ni++) {
        float p0 = __expf(sacc[ni][0] - mn0);
        float p1 = __expf(sacc[ni][1] - mn0);
        float p2 = __expf(sacc[ni][2] - mn1);
        float p3 = __expf(sacc[ni][3] - mn1);
        sacc[ni][0] = p0; sacc[ni][1] = p1; sacc[ni][2] = p2; sacc[ni][3] = p3;
        ls0 += p0 + p1; ls1 += p2 + p3;
    }
    ls0 += __shfl_xor_sync(0xffffffffu, ls0, 1);
    ls0 += __shfl_xor_sync(0xffffffffu, ls0, 2);
    ls1 += __shfl_xor_sync(0xffffffffu, ls1, 1);
    ls1 += __shfl_xor_sync(0xffffffffu, ls1, 2);
    l[0] = l[0] * cs0 + ls0; m[0] = mn0;
    l[1] = l[1] * cs1 + ls1; m[1] = mn1;
#pragma unroll
    for (int nd = 0; nd < 8; nd++) {
        oacc[nd][0] *= cs0; oacc[nd][1] *= cs0;
        oacc[nd][2] *= cs1; oacc[nd][3] *= cs1;
    }

    uint32_t vbase = kst + 18432;
    int jrow = ((g & 1) << 3) + w;
    int dcol = (g >> 1) * 16;
#pragma unroll
    for (int kk = 0; kk < NKK; kk++) {
        float* s0 = sacc[2 * kk];
        float* s1 = sacc[2 * kk + 1];
        uint32_t pa[4];
        pa[0] = packh(s0[0], s0[1]); pa[1] = packh(s0[2], s0[3]);
        pa[2] = packh(s1[0], s1[1]); pa[3] = packh(s1[2], s1[3]);
#pragma unroll
        for (int gv = 0; gv < 2; gv++) {
            uint32_t vh4[2][4];
#pragma unroll
            for (int u = 0; u < 2; u++) {
                int nd2 = gv * 2 + u;
                ldmx4t(vh4[u], vbase + (colbase + kk * 16 + jrow) * 144 + nd2 * 32 + dcol);
            }
#pragma unroll
            for (int u = 0; u < 2; u++) {
                int nd2 = gv * 2 + u;
                mma16816(oacc[nd2 * 2],     pa, vh4[u]);
                mma16816(oacc[nd2 * 2 + 1], pa, vh4[u] + 2);
            }
        }
    }
}

__global__ __launch_bounds__(512, 1)
void attn_mma()
{
    extern __shared__ __align__(16) char sm[];
    uint32_t smb = smem_u32(sm);
    int tid = threadIdx.x, lane = tid & 31, wid = tid >> 5;
    int rg = wid >> 1, ch2 = wid & 1;
    int qb = blockIdx.x, bh = blockIdx.y;

    size_t qoff = ((size_t)bh * TSEQ + (size_t)qb * 128) * HD;
    for (int c = tid; c < 1024; c += 512) {
        int row = c >> 3, ch = c & 7;
        *(uint4*)(sm + SMQ + row * 144 + ch * 16) =
            *(const uint4*)&g_q16[qoff + row * HD + ch * 8];
    }

    float oacc[8][4];
#pragma unroll
    for (int nd = 0; nd < 8; nd++)
#pragma unroll
        for (int q = 0; q < 4; q++) oacc[nd][q] = 0.f;
    float m[2] = { -1e30f, -1e30f }, l[2] = { 0.f, 0.f };

    int kb_lo = (qb - 2 > 0) ? qb - 2 : 0;
    int blocks[4], bcols[4], ndense = 0;
    for (int kb = kb_lo; kb <= qb; kb++) { blocks[ndense] = kb; bcols[ndense] = 128; ndense++; }
    if (kb_lo > 0) { blocks[ndense] = 0; bcols[ndense] = 16; ndense++; }

    auto stage_kv = [&](int st, int idx) {
        int kb = blocks[idx];
        int nr = (bcols[idx] == 128) ? 128 : 16;
        uint32_t base = smb + SMKV + st * STAGEKV;
        const __half* srcs[2] = { g_k16, g_v16 };
#pragma unroll
        for (int mm = 0; mm < 2; mm++) {
            const __half* src =
                srcs[mm] + ((size_t)bh * TSEQ + (size_t)kb * 128) * HD;
            for (int c = tid; c < nr * 8; c += 512) {
                int row = c >> 3, ch = c & 7;
                cpasync16(base + mm * 18432 + row * 144 + ch * 16,
                          src + row * HD + ch * 8);
            }
        }
    };

    stage_kv(0, 0); CP_COMMIT();
    int i0 = qb * 128 + rg * 16 + (lane >> 2);

    for (int it = 0; it < ndense; it++) {
        __syncthreads();
        if (it + 1 < ndense) { stage_kv((it + 1) & 1, it + 1); CP_COMMIT(); CP_WAIT1(); }
        else CP_WAIT0();
        __syncthreads();
        uint32_t kst = smb + SMKV + (it & 1) * STAGEKV;
        if (bcols[it] == 128)
            dense_block<8>(smb, kst, lane, rg, ch2 * 64, i0,
                           blocks[it] * 128 + ch2 * 64, oacc, m, l);
        else if (ch2 == 0)
            dense_block<2>(smb, kst, lane, rg, 0, i0, 0, oacc, m, l);
    }

    // strided diagonals: warp pair splits kb even/odd
    int nkb = qb - 2;
    float* Sst = (float*)(sm + SST_OFF);
    if (nkb > 0) {
        int part = lane & 3;
        for (int pass = 0; pass < 2; pass++) {
            int rloc = rg * 16 + pass * 8 + (lane >> 2);
            for (int kb = ch2; kb < nkb; kb += 2) {
                float sc;
                if (kb == 0 && rloc < 16) {
                    sc = -1e30f;
                } else {
                    int j = kb * 128 + rloc;
                    size_t kbase = ((size_t)bh * TSEQ + j) * HD + part * 16;
                    uint32_t qb0 = smb + SMQ + rloc * 144 + part * 32;
                    float sum = 0.f;
#pragma unroll
                    for (int seg = 0; seg < 2; seg++) {
                        uint32_t q4[4];
                        asm volatile("ld.shared.v4.b32 {%0,%1,%2,%3}, [%4];"
                            : "=r"(q4[0]), "=r"(q4[1]), "=r"(q4[2]), "=r"(q4[3])
                            : "r"(qb0 + seg * 16));
                        uint4 k4 = *(const uint4*)&g_k16[kbase + seg * 8];
                        const uint32_t* kp = (const uint32_t*)&k4;
#pragma unroll
                        for (int u = 0; u < 4; u++) {
                            float2 qf = h2f2(q4[u]);
                            float2 kf = h2f2(kp[u]);
                            sum += qf.x * kf.x + qf.y * kf.y;
                        }
                    }
                    sum += __shfl_xor_sync(0xffffffffu, sum, 1);
                    sum += __shfl_xor_sync(0xffffffffu, sum, 2);
                    sc = sum * SCALE;
                }
                if (part == 0) Sst[rloc * 33 + kb] = sc;
            }
        }
        __syncwarp();

#pragma unroll
        for (int h = 0; h < 2; h++) {
            int r = rg * 16 + (lane >> 2) + h * 8;
            float mo = m[h], mx = mo;
            for (int kb = ch2; kb < nkb; kb += 2)
                mx = fmaxf(mx, Sst[r * 33 + kb]);
            mx = fmaxf(mx, -1e28f);
            float cs = __expf(mo - mx);
            float ls = 0.f;
#pragma unroll
            for (int nd = 0; nd < 8; nd++) {
                oacc[nd][h * 2 + 0] *= cs;
                oacc[nd][h * 2 + 1] *= cs;
            }
            for (int kb = ch2; kb < nkb; kb += 2) {
                float p = __expf(Sst[r * 33 + kb] - mx);
                ls += p;
                if (p > 0.f) {
                    int j = kb * 128 + r;
                    size_t vb = ((size_t)bh * TSEQ + j) * HD;
#pragma unroll
                    for (int nd = 0; nd < 8; nd++) {
                        int d0 = nd * 8 + (lane & 3) * 2;
                        float2 vf = h2f2(*(const uint32_t*)&g_v16[vb + d0]);
                        oacc[nd][h * 2 + 0] += p * vf.x;
                        oacc[nd][h * 2 + 1] += p * vf.y;
                    }
                }
            }
            m[h] = mx;
            l[h] = l[h] * cs + ls;
        }
    }

    // pairwise split-softmax merge, then epilogue
    __syncthreads();
    {
        char* mb = sm + SMKV + wid * MERGE_B;
#pragma unroll
        for (int h = 0; h < 2; h++) {
            int row = (lane >> 2) + h * 8;
#pragma unroll
            for (int nd = 0; nd < 8; nd++) {
                int col = nd * 8 + (lane & 3) * 2;
                *(float2*)(mb + (row * 64 + col) * 4) =
                    make_float2(oacc[nd][h * 2], oacc[nd][h * 2 + 1]);
            }
            if ((lane & 3) == 0)
                *(float2*)(mb + 4096 + row * 8) = make_float2(m[h], l[h]);
        }
    }
    __syncthreads();
    if (ch2 == 0) {
        char* pb = sm + SMKV + (wid + 1) * MERGE_B;
        int b = bh >> 4, head = bh & 15;
#pragma unroll
        for (int h = 0; h < 2; h++) {
            int row = (lane >> 2) + h * 8;
            float2 ml = *(float2*)(pb + 4096 + row * 8);
            float mx = fmaxf(m[h], ml.x);
            float f0 = __expf(m[h] - mx), f1 = __expf(ml.x - mx);
            float L = l[h] * f0 + ml.y * f1;
            float inv = 1.f / L;
            int i = qb * 128 + rg * 16 + row;
            size_t row_off = ((size_t)(b * TSEQ + i)) * CEMB + head * HD;
#pragma unroll
            for (int nd = 0; nd < 8; nd++) {
                int col = nd * 8 + (lane & 3) * 2;
                float2 o1 = *(float2*)(pb + (row * 64 + col) * 4);
                float y0 = (oacc[nd][h * 2 + 0] * f0 + o1.x * f1) * inv;
                float y1 = (oacc[nd][h * 2 + 1] * f0 + o1.y * f1) * inv;
                *(uint32_t*)&g_y16[row_off + col] = packh(y0, y1);
            }
        }
    }
}

// ---------------- launch -------------------------------------------------------
extern "C" void kernel_launch(void* const* d_in, const int* in_sizes, int n_in,
                              void* d_out, int out_size)
{
    const float* x      = (const float*)d_in[0];
    const float* w_qkv  = (const float*)d_in[1];
    const float* b_qkv  = (const float*)d_in[2];
    const float* w_proj = (const float*)d_in[3];
    const float* b_proj = (const float*)d_in[4];
    float* out = (float*)d_out;

    cudaFuncSetAttribute(gemm_mma<0>,
                         cudaFuncAttributeMaxDynamicSharedMemorySize, GSMEM);
    cudaFuncSetAttribute(gemm_mma<1>,
                         cudaFuncAttributeMaxDynamicSharedMemorySize, GSMEM);
    cudaFuncSetAttribute(attn_mma,
                         cudaFuncAttributeMaxDynamicSharedMemorySize, ATTN_SMEM2);

    int n_x = MROWS * CEMB;
    conv_f16_x<<<n_x / 4 / 256, 256>>>(x, n_x);
    conv_f16_T<0><<<dim3(3 * CEMB / 32, CEMB / 32), 256>>>(w_qkv, CEMB, 3 * CEMB);
    conv_f16_T<1><<<dim3(CEMB / 32, CEMB / 32), 256>>>(w_proj, CEMB, CEMB);

    // 1) QKV GEMM -> Q/K/V fp16
    gemm_mma<0><<<dim3(3 * CEMB / 128, MROWS / 128), 256, GSMEM>>>(b_qkv, nullptr);

    // 2) fp16 HMMA block-sparse flash attention -> y16
    attn_mma<<<dim3(TSEQ / 128, BATCH * NH), 512, ATTN_SMEM2>>>();

    // 3) output projection -> out
    gemm_mma<1><<<dim3(CEMB / 128, MROWS / 128), 256, GSMEM>>>(b_proj, out);
}

// round 9
// speedup vs baseline: 2.4164x; 1.0874x over previous
#include <cuda_runtime.h>
#include <cuda_fp16.h>
#include <cstdint>
#include <math.h>

#define BATCH 2
#define TSEQ  4096
#define NH    16
#define HD    64
#define CEMB  1024
#define MROWS (BATCH*TSEQ)          // 8192
#define SCALE 0.125f                // 1/sqrt(64)
#define SCALE2 0.1803368801111204f  // SCALE * log2(e)

// ---------------- scratch (fp16 operands) --------------------------------------
__device__ __half g_x16[(size_t)MROWS*CEMB];
__device__ __half g_y16[(size_t)MROWS*CEMB];
__device__ __half g_wq16[(size_t)3*CEMB*CEMB];   // [N,K] K-major
__device__ __half g_wp16[(size_t)CEMB*CEMB];
__device__ __half g_q16[(size_t)BATCH*NH*TSEQ*HD];
__device__ __half g_k16[(size_t)BATCH*NH*TSEQ*HD];
__device__ __half g_v16[(size_t)BATCH*NH*TSEQ*HD];

// ---------------- PTX helpers --------------------------------------------------
__device__ __forceinline__ uint32_t smem_u32(const void* p) {
    uint32_t a;
    asm("{ .reg .u64 t; cvta.to.shared.u64 t, %1; cvt.u32.u64 %0, t; }"
        : "=r"(a) : "l"(p));
    return a;
}
__device__ __forceinline__ void cpasync16(uint32_t saddr, const void* g) {
    asm volatile("cp.async.cg.shared.global [%0], [%1], 16;"
                 :: "r"(saddr), "l"(g) : "memory");
}
#define CP_COMMIT() asm volatile("cp.async.commit_group;" ::: "memory")
#define CP_WAIT2()  asm volatile("cp.async.wait_group 2;" ::: "memory")
#define CP_WAIT1()  asm volatile("cp.async.wait_group 1;" ::: "memory")
#define CP_WAIT0()  asm volatile("cp.async.wait_group 0;" ::: "memory")

__device__ __forceinline__ void ldmx4(uint32_t* r, uint32_t addr) {
    asm volatile("ldmatrix.sync.aligned.m8n8.x4.shared.b16 {%0,%1,%2,%3}, [%4];"
        : "=r"(r[0]), "=r"(r[1]), "=r"(r[2]), "=r"(r[3]) : "r"(addr));
}
__device__ __forceinline__ void ldmx2(uint32_t* r, uint32_t addr) {
    asm volatile("ldmatrix.sync.aligned.m8n8.x2.shared.b16 {%0,%1}, [%2];"
        : "=r"(r[0]), "=r"(r[1]) : "r"(addr));
}
__device__ __forceinline__ void ldmx4t(uint32_t* r, uint32_t addr) {
    asm volatile("ldmatrix.sync.aligned.m8n8.x4.trans.shared.b16 {%0,%1,%2,%3}, [%4];"
        : "=r"(r[0]), "=r"(r[1]), "=r"(r[2]), "=r"(r[3]) : "r"(addr));
}
__device__ __forceinline__ void mma16816(float* d, const uint32_t* a,
                                         const uint32_t* b) {
    asm volatile(
        "mma.sync.aligned.m16n8k16.row.col.f32.f16.f16.f32 "
        "{%0,%1,%2,%3}, {%4,%5,%6,%7}, {%8,%9}, {%0,%1,%2,%3};"
        : "+f"(d[0]), "+f"(d[1]), "+f"(d[2]), "+f"(d[3])
        : "r"(a[0]), "r"(a[1]), "r"(a[2]), "r"(a[3]), "r"(b[0]), "r"(b[1]));
}

__device__ __forceinline__ float ex2(float x) {
    float r;
    asm("ex2.approx.ftz.f32 %0, %1;" : "=f"(r) : "f"(x));
    return r;
}
__device__ __forceinline__ float2 h2f2(uint32_t u) {
    __half2 h = *(__half2*)&u;
    return __half22float2(h);
}
__device__ __forceinline__ uint32_t packh(float x, float y) {
    __half2 t = __floats2half2_rn(x, y);
    return *(uint32_t*)&t;
}

// ---------------- conversion kernels -------------------------------------------
__global__ void conv_f16_x(const float* __restrict__ src, int n) {
    int i = (blockIdx.x * 256 + threadIdx.x) * 4;
    if (i < n) {
        float4 v = *(const float4*)&src[i];
        uint2 p;
        p.x = packh(v.x, v.y);
        p.y = packh(v.z, v.w);
        *(uint2*)&g_x16[i] = p;
    }
}
template <int W>
__global__ void conv_f16_T(const float* __restrict__ w, int K, int N) {
    __shared__ float t[32][33];
    __half* dT = (W == 0) ? g_wq16 : g_wp16;
    int n0 = blockIdx.x * 32, k0 = blockIdx.y * 32;
    int tx = threadIdx.x & 31, ty = threadIdx.x >> 5;
    for (int r = ty; r < 32; r += 8)
        t[r][tx] = w[(size_t)(k0 + r) * N + n0 + tx];
    __syncthreads();
    for (int r = ty; r < 32; r += 8)
        dT[(size_t)(n0 + r) * K + k0 + tx] = __float2half_rn(t[tx][r]);
}

// ---------------- fp16 GEMM, 3-stage cp.async, 2 CTAs/SM -----------------------
#define BK    64
#define ROWB  144
#define MATB  (128*ROWB)            // 18432
#define STAGEB (2*MATB)             // 36864
#define GSMEM (3*STAGEB)            // 110592

template <int MODE>
__global__ __launch_bounds__(256, 2)
void gemm_mma(const float* __restrict__ bias, float* __restrict__ out)
{
    extern __shared__ __align__(16) char sm[];
    uint32_t smb = smem_u32(sm);

    const __half* A16 = (MODE == 0) ? g_x16 : g_y16;
    const __half* B16 = (MODE == 0) ? g_wq16 : g_wp16;

    int tid = threadIdx.x;
    int wid = tid >> 5, lane = tid & 31;
    int wm = wid >> 2, wn = wid & 3;
    int mBase = blockIdx.y * 128, nBase = blockIdx.x * 128;

    float acc[4][4][4];
#pragma unroll
    for (int mi = 0; mi < 4; mi++)
#pragma unroll
        for (int ni = 0; ni < 4; ni++)
#pragma unroll
            for (int q = 0; q < 4; q++) acc[mi][ni][q] = 0.f;

    auto load_stage = [&](int st, int kt) {
        int k0 = kt * BK;
        uint32_t sb = smb + st * STAGEB;
#pragma unroll
        for (int c = tid; c < 1024; c += 256) {
            int row = c >> 3, ch = c & 7;
            cpasync16(sb + row * ROWB + ch * 16,
                      A16 + (size_t)(mBase + row) * CEMB + k0 + ch * 8);
        }
#pragma unroll
        for (int c = tid; c < 1024; c += 256) {
            int row = c >> 3, ch = c & 7;
            cpasync16(sb + MATB + row * ROWB + ch * 16,
                      B16 + (size_t)(nBase + row) * CEMB + k0 + ch * 8);
        }
    };

    int g = lane >> 3, w = lane & 7;
    uint32_t a_row = (wm * 64 + ((g & 1) << 3) + w) * ROWB;
    uint32_t b_row = (wn * 32 + w) * ROWB;
    uint32_t ka_off = ((g >> 1) << 3) * 2;
    uint32_t kb_off = ((g & 1) << 3) * 2;

    load_stage(0, 0); CP_COMMIT();
    load_stage(1, 1); CP_COMMIT();

    for (int kt = 0; kt < 16; kt++) {
        if (kt < 15) CP_WAIT1(); else CP_WAIT0();
        __syncthreads();
        if (kt + 2 < 16) { load_stage((kt + 2) % 3, kt + 2); CP_COMMIT(); }

        uint32_t bA = smb + (kt % 3) * STAGEB;
        uint32_t bB = bA + MATB;

#pragma unroll
        for (int ks = 0; ks < 4; ks++) {
            uint32_t ka = ks * 32 + ka_off;
            uint32_t kb = ks * 32 + kb_off;
            uint32_t ah[4][4], bh[4][2];
#pragma unroll
            for (int mi = 0; mi < 4; mi++)
                ldmx4(ah[mi], bA + a_row + mi * 16 * ROWB + ka);
#pragma unroll
            for (int ni = 0; ni < 4; ni++)
                ldmx2(bh[ni], bB + b_row + ni * 8 * ROWB + kb);
#pragma unroll
            for (int mi = 0; mi < 4; mi++)
#pragma unroll
                for (int ni = 0; ni < 4; ni++)
                    mma16816(acc[mi][ni], ah[mi], bh[ni]);
        }
        __syncthreads();
    }

    int r_in = lane >> 2, c_in = (lane & 3) * 2;
#pragma unroll
    for (int mi = 0; mi < 4; mi++) {
#pragma unroll
        for (int half = 0; half < 2; half++) {
            int m = mBase + wm * 64 + mi * 16 + r_in + half * 8;
#pragma unroll
            for (int ni = 0; ni < 4; ni++) {
                int n = nBase + wn * 32 + ni * 8 + c_in;
                float v0 = acc[mi][ni][half * 2 + 0] + bias[n];
                float v1 = acc[mi][ni][half * 2 + 1] + bias[n + 1];
                if (MODE == 0) {
                    int b = m >> 12, t = m & 4095;
                    int sect = n >> 10, cc = n & 1023;
                    int head = cc >> 6, d0 = cc & 63;
                    size_t off = (((size_t)(b * NH + head)) * TSEQ + t) * HD + d0;
                    __half* dst = (sect == 0) ? g_q16 : (sect == 1) ? g_k16 : g_v16;
                    *(uint32_t*)&dst[off] = packh(v0, v1);
                } else {
                    *(float2*)&out[(size_t)m * CEMB + n] = make_float2(v0, v1);
                }
            }
        }
    }
}

// ---------------- fp16 HMMA block-sparse flash attention -----------------------
// 512 thr = 16 warps: 8 row-groups x 2 col-halves. All dense blocks staged to
// dedicated buffers; triangle blocks processed in one sync-free stretch.
#define SMQ    0
#define SB0    18432
#define SB1    55296
#define SB2    92160
#define SBG    129024                       // K 16 rows (2304) + V (2304)
#define SST    133632                       // 128*33*4 = 16896
#define SMRG   18432                        // merge slabs overlay SB0/SB1
#define MERGE_B 4352
#define ATTN_SM (SST + 16896)               // 150528

// MODE: 0 = fully valid, 1 = upper (c>=r, diff<=256), 2 = lower (causal),
//       3 = general mask
template <int NNI, int MODE>
__device__ __forceinline__ void dense_block(
    uint32_t smb, uint32_t kst, uint32_t vst, int lane, int rg, int colbase,
    int i0, int jb, float (&oacc)[8][4], float (&m)[2], float (&l)[2])
{
    const int NKK = NNI / 2;
    int g = lane >> 3, w = lane & 7;
    uint32_t arow = smb + SMQ + (rg * 16 + ((g & 1) << 3) + w) * 144;
    uint32_t ka = (g >> 1) * 16;
    uint32_t kboff = (g & 1) * 16;
    int r0 = rg * 16;

    unsigned skipmask = 0;
    if (MODE == 1) {
#pragma unroll
        for (int ni = 0; ni < NNI; ni++)
            if (colbase + ni * 8 + 7 < r0) skipmask |= 1u << ni;
    } else if (MODE == 2) {
#pragma unroll
        for (int ni = 0; ni < NNI; ni++)
            if (colbase + ni * 8 > r0 + 15) skipmask |= 1u << ni;
    }

    float sacc[NNI][4];
#pragma unroll
    for (int ni = 0; ni < NNI; ni++)
#pragma unroll
        for (int q = 0; q < 4; q++) sacc[ni][q] = 0.f;

#pragma unroll
    for (int ks = 0; ks < 4; ks++) {
        uint32_t q4[4];
        ldmx4(q4, arow + ks * 32 + ka);
#pragma unroll
        for (int ni = 0; ni < NNI; ni++) {
            if ((skipmask >> ni) & 1) continue;
            uint32_t kb2[2];
            ldmx2(kb2, kst + (colbase + ni * 8 + w) * 144 + kboff + ks * 32);
            mma16816(sacc[ni], q4, kb2);
        }
    }

    int c0 = (lane & 3) * 2;
    float mb0 = -1e30f, mb1 = -1e30f;
#pragma unroll
    for (int ni = 0; ni < NNI; ni++) {
        if ((skipmask >> ni) & 1) continue;
        int jB = jb + ni * 8 + c0;
#pragma unroll
        for (int q = 0; q < 4; q++) {
            int jj = jB + (q & 1);
            int ii = (q < 2) ? i0 : i0 + 8;
            bool ok;
            if (MODE == 0) ok = true;
            else if (MODE == 1) ok = (ii - jj) <= 256;
            else if (MODE == 2) ok = jj <= ii;
            else {
                int diff = ii - jj;
                ok = diff >= 0 && (diff < 256 || (diff & 127) == 0 || jj < 16);
            }
            sacc[ni][q] = ok ? sacc[ni][q] * SCALE2 : -1e30f;
        }
        mb0 = fmaxf(mb0, fmaxf(sacc[ni][0], sacc[ni][1]));
        mb1 = fmaxf(mb1, fmaxf(sacc[ni][2], sacc[ni][3]));
    }
    mb0 = fmaxf(mb0, __shfl_xor_sync(0xffffffffu, mb0, 1));
    mb0 = fmaxf(mb0, __shfl_xor_sync(0xffffffffu, mb0, 2));
    mb1 = fmaxf(mb1, __shfl_xor_sync(0xffffffffu, mb1, 1));
    mb1 = fmaxf(mb1, __shfl_xor_sync(0xffffffffu, mb1, 2));

    float mn0 = fmaxf(fmaxf(m[0], mb0), -1e28f);
    float mn1 = fmaxf(fmaxf(m[1], mb1), -1e28f);
    float cs0 = ex2(m[0] - mn0), cs1 = ex2(m[1] - mn1);
    float ls0 = 0.f, ls1 = 0.f;
#pragma unroll
    for (int ni = 0; ni < NNI; ni++) {
        if ((skipmask >> ni) & 1) {
            sacc[ni][0] = sacc[ni][1] = sacc[ni][2] = sacc[ni][3] = 0.f;
            continue;
        }
        float p0 = ex2(sacc[ni][0] - mn0);
        float p1 = ex2(sacc[ni][1] - mn0);
        float p2 = ex2(sacc[ni][2] - mn1);
        float p3 = ex2(sacc[ni][3] - mn1);
        sacc[ni][0] = p0; sacc[ni][1] = p1; sacc[ni][2] = p2; sacc[ni][3] = p3;
        ls0 += p0 + p1; ls1 += p2 + p3;
    }
    ls0 += __shfl_xor_sync(0xffffffffu, ls0, 1);
    ls0 += __shfl_xor_sync(0xffffffffu, ls0, 2);
    ls1 += __shfl_xor_sync(0xffffffffu, ls1, 1);
    ls1 += __shfl_xor_sync(0xffffffffu, ls1, 2);
    l[0] = l[0] * cs0 + ls0; m[0] = mn0;
    l[1] = l[1] * cs1 + ls1; m[1] = mn1;
#pragma unroll
    for (int nd = 0; nd < 8; nd++) {
        oacc[nd][0] *= cs0; oacc[nd][1] *= cs0;
        oacc[nd][2] *= cs1; oacc[nd][3] *= cs1;
    }

    int jrow = ((g & 1) << 3) + w;
    int dcol = (g >> 1) * 16;
#pragma unroll
    for (int kk = 0; kk < NKK; kk++) {
        if (((skipmask >> (2 * kk)) & 3u) == 3u) continue;
        float* s0 = sacc[2 * kk];
        float* s1 = sacc[2 * kk + 1];
        uint32_t pa[4];
        pa[0] = packh(s0[0], s0[1]); pa[1] = packh(s0[2], s0[3]);
        pa[2] = packh(s1[0], s1[1]); pa[3] = packh(s1[2], s1[3]);
#pragma unroll
        for (int gv = 0; gv < 2; gv++) {
            uint32_t vh4[2][4];
#pragma unroll
            for (int u = 0; u < 2; u++) {
                int nd2 = gv * 2 + u;
                ldmx4t(vh4[u], vst + (colbase + kk * 16 + jrow) * 144 + nd2 * 32 + dcol);
            }
#pragma unroll
            for (int u = 0; u < 2; u++) {
                int nd2 = gv * 2 + u;
                mma16816(oacc[nd2 * 2],     pa, vh4[u]);
                mma16816(oacc[nd2 * 2 + 1], pa, vh4[u] + 2);
            }
        }
    }
}

__global__ __launch_bounds__(512, 1)
void attn_mma()
{
    extern __shared__ __align__(16) char sm[];
    uint32_t smb = smem_u32(sm);
    int tid = threadIdx.x, lane = tid & 31, wid = tid >> 5;
    int rg = wid >> 1, ch2 = wid & 1;
    int qb = blockIdx.x, bh = blockIdx.y;

    auto stage_rows = [&](uint32_t dst, const __half* src, int nrows) {
        for (int c = tid; c < nrows * 8; c += 512) {
            int row = c >> 3, ch = c & 7;
            cpasync16(dst + row * 144 + ch * 16, src + (size_t)row * HD + ch * 8);
        }
    };
    size_t hb = (size_t)bh * TSEQ * HD;
    const __half* Qg = g_q16 + hb + (size_t)qb * 128 * HD;

    float oacc[8][4];
#pragma unroll
    for (int nd = 0; nd < 8; nd++)
#pragma unroll
        for (int q = 0; q < 4; q++) oacc[nd][q] = 0.f;
    float m[2] = { -1e30f, -1e30f }, l[2] = { 0.f, 0.f };
    int i0 = qb * 128 + rg * 16 + (lane >> 2);

    if (qb >= 3) {
        stage_rows(smb + SMQ, Qg, 128);
        stage_rows(smb + SB1,         g_k16 + hb + (size_t)(qb - 1) * 128 * HD, 128);
        stage_rows(smb + SB1 + 18432, g_v16 + hb + (size_t)(qb - 1) * 128 * HD, 128);
        CP_COMMIT();
        stage_rows(smb + SB0,         g_k16 + hb + (size_t)(qb - 2) * 128 * HD, 128);
        stage_rows(smb + SB0 + 18432, g_v16 + hb + (size_t)(qb - 2) * 128 * HD, 128);
        CP_COMMIT();
        stage_rows(smb + SB2,         g_k16 + hb + (size_t)qb * 128 * HD, 128);
        stage_rows(smb + SB2 + 18432, g_v16 + hb + (size_t)qb * 128 * HD, 128);
        stage_rows(smb + SBG,        g_k16 + hb, 16);
        stage_rows(smb + SBG + 2304, g_v16 + hb, 16);
        CP_COMMIT();

        CP_WAIT2(); __syncthreads();
        dense_block<8, 0>(smb, smb + SB1, smb + SB1 + 18432, lane, rg, ch2 * 64,
                          i0, (qb - 1) * 128 + ch2 * 64, oacc, m, l);
        CP_WAIT0(); __syncthreads();
        dense_block<8, 1>(smb, smb + SB0, smb + SB0 + 18432, lane, rg, ch2 * 64,
                          i0, (qb - 2) * 128 + ch2 * 64, oacc, m, l);
        dense_block<8, 2>(smb, smb + SB2, smb + SB2 + 18432, lane, rg, ch2 * 64,
                          i0, qb * 128 + ch2 * 64, oacc, m, l);
        if (ch2 == 0)
            dense_block<2, 0>(smb, smb + SBG, smb + SBG + 2304, lane, rg, 0,
                              i0, 0, oacc, m, l);
    } else {
        stage_rows(smb + SMQ, Qg, 128);
        stage_rows(smb + SB0, g_k16 + hb, 128);
        stage_rows(smb + SB0 + 18432, g_v16 + hb, 128);
        CP_COMMIT();
        if (qb >= 1) {
            stage_rows(smb + SB1, g_k16 + hb + (size_t)128 * HD, 128);
            stage_rows(smb + SB1 + 18432, g_v16 + hb + (size_t)128 * HD, 128);
        }
        CP_COMMIT();
        if (qb >= 2) {
            stage_rows(smb + SB2, g_k16 + hb + (size_t)256 * HD, 128);
            stage_rows(smb + SB2 + 18432, g_v16 + hb + (size_t)256 * HD, 128);
        }
        CP_COMMIT();
        CP_WAIT0(); __syncthreads();
        uint32_t bufs[3] = { smb + SB0, smb + SB1, smb + SB2 };
        for (int kb = 0; kb <= qb; kb++)
            dense_block<8, 3>(smb, bufs[kb], bufs[kb] + 18432, lane, rg, ch2 * 64,
                              i0, kb * 128 + ch2 * 64, oacc, m, l);
    }

    // strided diagonals (kb 0..qb-3); warp pair splits even/odd
    int nkb = qb - 2;
    float* Sst = (float*)(sm + SST);
    if (nkb > 0) {
        int part = lane & 3;
        for (int pass = 0; pass < 2; pass++) {
            int rloc = rg * 16 + pass * 8 + (lane >> 2);
            for (int kb = ch2; kb < nkb; kb += 2) {
                float sc;
                if (kb == 0 && rloc < 16) {
                    sc = -1e30f;
                } else {
                    int j = kb * 128 + rloc;
                    size_t kbase = hb + (size_t)j * HD + part * 16;
                    uint32_t qb0 = smb + SMQ + rloc * 144 + part * 32;
                    float sum = 0.f;
#pragma unroll
                    for (int seg = 0; seg < 2; seg++) {
                        uint32_t q4[4];
                        asm volatile("ld.shared.v4.b32 {%0,%1,%2,%3}, [%4];"
                            : "=r"(q4[0]), "=r"(q4[1]), "=r"(q4[2]), "=r"(q4[3])
                            : "r"(qb0 + seg * 16));
                        uint4 k4 = *(const uint4*)&g_k16[kbase + seg * 8];
                        const uint32_t* kp = (const uint32_t*)&k4;
#pragma unroll
                        for (int u = 0; u < 4; u++) {
                            float2 qf = h2f2(q4[u]);
                            float2 kf = h2f2(kp[u]);
                            sum += qf.x * kf.x + qf.y * kf.y;
                        }
                    }
                    sum += __shfl_xor_sync(0xffffffffu, sum, 1);
                    sum += __shfl_xor_sync(0xffffffffu, sum, 2);
                    sc = sum * SCALE2;
                }
                if (part == 0) Sst[rloc * 33 + kb] = sc;
            }
        }
        __syncwarp();

#pragma unroll
        for (int h = 0; h < 2; h++) {
            int r = rg * 16 + (lane >> 2) + h * 8;
            float mo = m[h], mx = mo;
            for (int kb = ch2; kb < nkb; kb += 2)
                mx = fmaxf(mx, Sst[r * 33 + kb]);
            mx = fmaxf(mx, -1e28f);
            float cs = ex2(mo - mx);
            float ls = 0.f;
#pragma unroll
            for (int nd = 0; nd < 8; nd++) {
                oacc[nd][h * 2 + 0] *= cs;
                oacc[nd][h * 2 + 1] *= cs;
            }
            for (int kb = ch2; kb < nkb; kb += 2) {
                float p = ex2(Sst[r * 33 + kb] - mx);
                ls += p;
                if (p > 0.f) {
                    int j = kb * 128 + r;
                    size_t vb = hb + (size_t)j * HD;
#pragma unroll
                    for (int nd = 0; nd < 8; nd++) {
                        int d0 = nd * 8 + (lane & 3) * 2;
                        float2 vf = h2f2(*(const uint32_t*)&g_v16[vb + d0]);
                        oacc[nd][h * 2 + 0] += p * vf.x;
                        oacc[nd][h * 2 + 1] += p * vf.y;
                    }
                }
            }
            m[h] = mx;
            l[h] = l[h] * cs + ls;
        }
    }

    // pairwise split-softmax merge, then epilogue
    __syncthreads();
    {
        char* mb = sm + SMRG + wid * MERGE_B;
#pragma unroll
        for (int h = 0; h < 2; h++) {
            int row = (lane >> 2) + h * 8;
#pragma unroll
            for (int nd = 0; nd < 8; nd++) {
                int col = nd * 8 + (lane & 3) * 2;
                *(float2*)(mb + (row * 64 + col) * 4) =
                    make_float2(oacc[nd][h * 2], oacc[nd][h * 2 + 1]);
            }
            if ((lane & 3) == 0)
                *(float2*)(mb + 4096 + row * 8) = make_float2(m[h], l[h]);
        }
    }
    __syncthreads();
    if (ch2 == 0) {
        char* pb = sm + SMRG + (wid + 1) * MERGE_B;
        int b = bh >> 4, head = bh & 15;
#pragma unroll
        for (int h = 0; h < 2; h++) {
            int row = (lane >> 2) + h * 8;
            float2 ml = *(float2*)(pb + 4096 + row * 8);
            float mx = fmaxf(m[h], ml.x);
            float f0 = ex2(m[h] - mx), f1 = ex2(ml.x - mx);
            float L = l[h] * f0 + ml.y * f1;
            float inv = 1.f / L;
            int i = qb * 128 + rg * 16 + row;
            size_t row_off = ((size_t)(b * TSEQ + i)) * CEMB + head * HD;
#pragma unroll
            for (int nd = 0; nd < 8; nd++) {
                int col = nd * 8 + (lane & 3) * 2;
                float2 o1 = *(float2*)(pb + (row * 64 + col) * 4);
                float y0 = (oacc[nd][h * 2 + 0] * f0 + o1.x * f1) * inv;
                float y1 = (oacc[nd][h * 2 + 1] * f0 + o1.y * f1) * inv;
                *(uint32_t*)&g_y16[row_off + col] = packh(y0, y1);
            }
        }
    }
}

// ---------------- launch -------------------------------------------------------
extern "C" void kernel_launch(void* const* d_in, const int* in_sizes, int n_in,
                              void* d_out, int out_size)
{
    const float* x      = (const float*)d_in[0];
    const float* w_qkv  = (const float*)d_in[1];
    const float* b_qkv  = (const float*)d_in[2];
    const float* w_proj = (const float*)d_in[3];
    const float* b_proj = (const float*)d_in[4];
    float* out = (float*)d_out;

    cudaFuncSetAttribute(gemm_mma<0>,
                         cudaFuncAttributeMaxDynamicSharedMemorySize, GSMEM);
    cudaFuncSetAttribute(gemm_mma<1>,
                         cudaFuncAttributeMaxDynamicSharedMemorySize, GSMEM);
    cudaFuncSetAttribute(attn_mma,
                         cudaFuncAttributeMaxDynamicSharedMemorySize, ATTN_SM);

    int n_x = MROWS * CEMB;
    conv_f16_x<<<n_x / 4 / 256, 256>>>(x, n_x);
    conv_f16_T<0><<<dim3(3 * CEMB / 32, CEMB / 32), 256>>>(w_qkv, CEMB, 3 * CEMB);
    conv_f16_T<1><<<dim3(CEMB / 32, CEMB / 32), 256>>>(w_proj, CEMB, CEMB);

    gemm_mma<0><<<dim3(3 * CEMB / 128, MROWS / 128), 256, GSMEM>>>(b_qkv, nullptr);
    attn_mma<<<dim3(TSEQ / 128, BATCH * NH), 512, ATTN_SM>>>();
    gemm_mma<1><<<dim3(CEMB / 128, MROWS / 128), 256, GSMEM>>>(b_proj, out);
}

// round 10
// speedup vs baseline: 2.4416x; 1.0105x over previous
#include <cuda_runtime.h>
#include <cuda_fp16.h>
#include <cstdint>
#include <math.h>

#define BATCH 2
#define TSEQ  4096
#define NH    16
#define HD    64
#define CEMB  1024
#define MROWS (BATCH*TSEQ)          // 8192
#define SCALE2 0.1803368801111204f  // (1/8) * log2(e)

// ---------------- scratch (fp16 operands) --------------------------------------
__device__ __half g_x16[(size_t)MROWS*CEMB];
__device__ __half g_y16[(size_t)MROWS*CEMB];
__device__ __half g_wq16[(size_t)3*CEMB*CEMB];   // [N,K] K-major
__device__ __half g_wp16[(size_t)CEMB*CEMB];
__device__ __half g_q16[(size_t)BATCH*NH*TSEQ*HD];
__device__ __half g_k16[(size_t)BATCH*NH*TSEQ*HD];
__device__ __half g_v16[(size_t)BATCH*NH*TSEQ*HD];

// ---------------- PTX helpers --------------------------------------------------
__device__ __forceinline__ uint32_t smem_u32(const void* p) {
    uint32_t a;
    asm("{ .reg .u64 t; cvta.to.shared.u64 t, %1; cvt.u32.u64 %0, t; }"
        : "=r"(a) : "l"(p));
    return a;
}
__device__ __forceinline__ void cpasync16(uint32_t saddr, const void* g) {
    asm volatile("cp.async.cg.shared.global [%0], [%1], 16;"
                 :: "r"(saddr), "l"(g) : "memory");
}
#define CP_COMMIT() asm volatile("cp.async.commit_group;" ::: "memory")
#define CP_WAIT2()  asm volatile("cp.async.wait_group 2;" ::: "memory")
#define CP_WAIT1()  asm volatile("cp.async.wait_group 1;" ::: "memory")
#define CP_WAIT0()  asm volatile("cp.async.wait_group 0;" ::: "memory")

__device__ __forceinline__ void ldmx4(uint32_t* r, uint32_t addr) {
    asm volatile("ldmatrix.sync.aligned.m8n8.x4.shared.b16 {%0,%1,%2,%3}, [%4];"
        : "=r"(r[0]), "=r"(r[1]), "=r"(r[2]), "=r"(r[3]) : "r"(addr));
}
__device__ __forceinline__ void ldmx2(uint32_t* r, uint32_t addr) {
    asm volatile("ldmatrix.sync.aligned.m8n8.x2.shared.b16 {%0,%1}, [%2];"
        : "=r"(r[0]), "=r"(r[1]) : "r"(addr));
}
__device__ __forceinline__ void ldmx4t(uint32_t* r, uint32_t addr) {
    asm volatile("ldmatrix.sync.aligned.m8n8.x4.trans.shared.b16 {%0,%1,%2,%3}, [%4];"
        : "=r"(r[0]), "=r"(r[1]), "=r"(r[2]), "=r"(r[3]) : "r"(addr));
}
__device__ __forceinline__ void mma16816(float* d, const uint32_t* a,
                                         const uint32_t* b) {
    asm volatile(
        "mma.sync.aligned.m16n8k16.row.col.f32.f16.f16.f32 "
        "{%0,%1,%2,%3}, {%4,%5,%6,%7}, {%8,%9}, {%0,%1,%2,%3};"
        : "+f"(d[0]), "+f"(d[1]), "+f"(d[2]), "+f"(d[3])
        : "r"(a[0]), "r"(a[1]), "r"(a[2]), "r"(a[3]), "r"(b[0]), "r"(b[1]));
}

__device__ __forceinline__ float ex2(float x) {
    float r;
    asm("ex2.approx.ftz.f32 %0, %1;" : "=f"(r) : "f"(x));
    return r;
}
__device__ __forceinline__ uint32_t ex2h2(uint32_t x) {
    uint32_t r;
    asm("ex2.approx.f16x2 %0, %1;" : "=r"(r) : "r"(x));
    return r;
}
__device__ __forceinline__ float2 h2f2(uint32_t u) {
    __half2 h = *(__half2*)&u;
    return __half22float2(h);
}
__device__ __forceinline__ uint32_t packh(float x, float y) {
    __half2 t = __floats2half2_rn(x, y);
    return *(uint32_t*)&t;
}

// ---------------- conversion kernels -------------------------------------------
__global__ void conv_f16_x(const float* __restrict__ src, int n) {
    int i = (blockIdx.x * 256 + threadIdx.x) * 4;
    if (i < n) {
        float4 v = *(const float4*)&src[i];
        uint2 p;
        p.x = packh(v.x, v.y);
        p.y = packh(v.z, v.w);
        *(uint2*)&g_x16[i] = p;
    }
}
template <int W>
__global__ void conv_f16_T(const float* __restrict__ w, int K, int N) {
    __shared__ float t[32][33];
    __half* dT = (W == 0) ? g_wq16 : g_wp16;
    int n0 = blockIdx.x * 32, k0 = blockIdx.y * 32;
    int tx = threadIdx.x & 31, ty = threadIdx.x >> 5;
    for (int r = ty; r < 32; r += 8)
        t[r][tx] = w[(size_t)(k0 + r) * N + n0 + tx];
    __syncthreads();
    for (int r = ty; r < 32; r += 8)
        dT[(size_t)(n0 + r) * K + k0 + tx] = __float2half_rn(t[tx][r]);
}

// ---------------- fp16 GEMM, 3-stage cp.async, 2 CTAs/SM -----------------------
#define BK    64
#define ROWB  144
#define MATB  (128*ROWB)            // 18432
#define STAGEB (2*MATB)             // 36864
#define GSMEM (3*STAGEB)            // 110592

template <int MODE>
__global__ __launch_bounds__(256, 2)
void gemm_mma(const float* __restrict__ bias, float* __restrict__ out)
{
    extern __shared__ __align__(16) char sm[];
    uint32_t smb = smem_u32(sm);

    const __half* A16 = (MODE == 0) ? g_x16 : g_y16;
    const __half* B16 = (MODE == 0) ? g_wq16 : g_wp16;

    int tid = threadIdx.x;
    int wid = tid >> 5, lane = tid & 31;
    int wm = wid >> 2, wn = wid & 3;
    int mBase = blockIdx.y * 128, nBase = blockIdx.x * 128;

    float acc[4][4][4];
#pragma unroll
    for (int mi = 0; mi < 4; mi++)
#pragma unroll
        for (int ni = 0; ni < 4; ni++)
#pragma unroll
            for (int q = 0; q < 4; q++) acc[mi][ni][q] = 0.f;

    auto load_stage = [&](int st, int kt) {
        int k0 = kt * BK;
        uint32_t sb = smb + st * STAGEB;
#pragma unroll
        for (int c = tid; c < 1024; c += 256) {
            int row = c >> 3, ch = c & 7;
            cpasync16(sb + row * ROWB + ch * 16,
                      A16 + (size_t)(mBase + row) * CEMB + k0 + ch * 8);
        }
#pragma unroll
        for (int c = tid; c < 1024; c += 256) {
            int row = c >> 3, ch = c & 7;
            cpasync16(sb + MATB + row * ROWB + ch * 16,
                      B16 + (size_t)(nBase + row) * CEMB + k0 + ch * 8);
        }
    };

    int g = lane >> 3, w = lane & 7;
    uint32_t a_row = (wm * 64 + ((g & 1) << 3) + w) * ROWB;
    uint32_t b_row = (wn * 32 + w) * ROWB;
    uint32_t ka_off = ((g >> 1) << 3) * 2;
    uint32_t kb_off = ((g & 1) << 3) * 2;

    load_stage(0, 0); CP_COMMIT();
    load_stage(1, 1); CP_COMMIT();

    for (int kt = 0; kt < 16; kt++) {
        if (kt < 15) CP_WAIT1(); else CP_WAIT0();
        __syncthreads();
        if (kt + 2 < 16) { load_stage((kt + 2) % 3, kt + 2); CP_COMMIT(); }

        uint32_t bA = smb + (kt % 3) * STAGEB;
        uint32_t bB = bA + MATB;

#pragma unroll
        for (int ks = 0; ks < 4; ks++) {
            uint32_t ka = ks * 32 + ka_off;
            uint32_t kb = ks * 32 + kb_off;
            uint32_t ah[4][4], bh[4][2];
#pragma unroll
            for (int mi = 0; mi < 4; mi++)
                ldmx4(ah[mi], bA + a_row + mi * 16 * ROWB + ka);
#pragma unroll
            for (int ni = 0; ni < 4; ni++)
                ldmx2(bh[ni], bB + b_row + ni * 8 * ROWB + kb);
#pragma unroll
            for (int mi = 0; mi < 4; mi++)
#pragma unroll
                for (int ni = 0; ni < 4; ni++)
                    mma16816(acc[mi][ni], ah[mi], bh[ni]);
        }
        __syncthreads();
    }

    int r_in = lane >> 2, c_in = (lane & 3) * 2;
#pragma unroll
    for (int mi = 0; mi < 4; mi++) {
#pragma unroll
        for (int half = 0; half < 2; half++) {
            int m = mBase + wm * 64 + mi * 16 + r_in + half * 8;
#pragma unroll
            for (int ni = 0; ni < 4; ni++) {
                int n = nBase + wn * 32 + ni * 8 + c_in;
                float v0 = acc[mi][ni][half * 2 + 0] + bias[n];
                float v1 = acc[mi][ni][half * 2 + 1] + bias[n + 1];
                if (MODE == 0) {
                    int b = m >> 12, t = m & 4095;
                    int sect = n >> 10, cc = n & 1023;
                    int head = cc >> 6, d0 = cc & 63;
                    size_t off = (((size_t)(b * NH + head)) * TSEQ + t) * HD + d0;
                    __half* dst = (sect == 0) ? g_q16 : (sect == 1) ? g_k16 : g_v16;
                    *(uint32_t*)&dst[off] = packh(v0, v1);
                } else {
                    *(float2*)&out[(size_t)m * CEMB + n] = make_float2(v0, v1);
                }
            }
        }
    }
}

// ---------------- fp16 HMMA block-sparse flash attention -----------------------
#define SMQ    0
#define SB0    18432
#define SB1    55296
#define SB2    92160
#define SBG    129024
#define SST    133632
#define SMRG   18432
#define MERGE_B 4352
#define ATTN_SM (SST + 16896)               // 150528

// MODE: 0 = fully valid, 1 = upper (diff<=256), 2 = lower (causal), 3 = general
template <int NNI, int MODE>
__device__ __forceinline__ void dense_block(
    uint32_t smb, uint32_t kst, uint32_t vst, int lane, int rg, int colbase,
    int i0, int jb, float (&oacc)[8][4], float (&m)[2], float (&l)[2])
{
    const int NKK = NNI / 2;
    int g = lane >> 3, w = lane & 7;
    uint32_t arow = smb + SMQ + (rg * 16 + ((g & 1) << 3) + w) * 144;
    uint32_t ka = (g >> 1) * 16;
    uint32_t kboff = (g & 1) * 16;
    int r0 = rg * 16;

    unsigned skipmask = 0;
    if (MODE == 1) {
#pragma unroll
        for (int ni = 0; ni < NNI; ni++)
            if (colbase + ni * 8 + 7 < r0) skipmask |= 1u << ni;
    } else if (MODE == 2) {
#pragma unroll
        for (int ni = 0; ni < NNI; ni++)
            if (colbase + ni * 8 > r0 + 15) skipmask |= 1u << ni;
    }

    float sacc[NNI][4];
#pragma unroll
    for (int ni = 0; ni < NNI; ni++)
#pragma unroll
        for (int q = 0; q < 4; q++) sacc[ni][q] = 0.f;

#pragma unroll
    for (int ks = 0; ks < 4; ks++) {
        uint32_t q4[4];
        ldmx4(q4, arow + ks * 32 + ka);
#pragma unroll
        for (int ni = 0; ni < NNI; ni++) {
            if ((skipmask >> ni) & 1) continue;
            uint32_t kb2[2];
            ldmx2(kb2, kst + (colbase + ni * 8 + w) * 144 + kboff + ks * 32);
            mma16816(sacc[ni], q4, kb2);
        }
    }

    int c0 = (lane & 3) * 2;
    float mb0 = -1e30f, mb1 = -1e30f;
#pragma unroll
    for (int ni = 0; ni < NNI; ni++) {
        if ((skipmask >> ni) & 1) continue;
        int jB = jb + ni * 8 + c0;
#pragma unroll
        for (int q = 0; q < 4; q++) {
            int jj = jB + (q & 1);
            int ii = (q < 2) ? i0 : i0 + 8;
            bool ok;
            if (MODE == 0) ok = true;
            else if (MODE == 1) ok = (ii - jj) <= 256;
            else if (MODE == 2) ok = jj <= ii;
            else {
                int diff = ii - jj;
                ok = diff >= 0 && (diff < 256 || (diff & 127) == 0 || jj < 16);
            }
            sacc[ni][q] = ok ? sacc[ni][q] * SCALE2 : -1e30f;
        }
        mb0 = fmaxf(mb0, fmaxf(sacc[ni][0], sacc[ni][1]));
        mb1 = fmaxf(mb1, fmaxf(sacc[ni][2], sacc[ni][3]));
    }
    mb0 = fmaxf(mb0, __shfl_xor_sync(0xffffffffu, mb0, 1));
    mb0 = fmaxf(mb0, __shfl_xor_sync(0xffffffffu, mb0, 2));
    mb1 = fmaxf(mb1, __shfl_xor_sync(0xffffffffu, mb1, 1));
    mb1 = fmaxf(mb1, __shfl_xor_sync(0xffffffffu, mb1, 2));

    float mn0 = fmaxf(fmaxf(m[0], mb0), -1e28f);
    float mn1 = fmaxf(fmaxf(m[1], mb1), -1e28f);
    float cs0 = ex2(m[0] - mn0), cs1 = ex2(m[1] - mn1);

    // probs via packed half2 ex2 -> directly in A-fragment layout
    uint32_t pp[NNI][2];
    float ls0 = 0.f, ls1 = 0.f;
#pragma unroll
    for (int ni = 0; ni < NNI; ni++) {
        if ((skipmask >> ni) & 1) { pp[ni][0] = 0u; pp[ni][1] = 0u; continue; }
        uint32_t a0 = packh(sacc[ni][0] - mn0, sacc[ni][1] - mn0);
        uint32_t a1 = packh(sacc[ni][2] - mn1, sacc[ni][3] - mn1);
        uint32_t p0 = ex2h2(a0), p1 = ex2h2(a1);
        pp[ni][0] = p0; pp[ni][1] = p1;
        float2 f0 = h2f2(p0), f1 = h2f2(p1);
        ls0 += f0.x + f0.y; ls1 += f1.x + f1.y;
    }
    ls0 += __shfl_xor_sync(0xffffffffu, ls0, 1);
    ls0 += __shfl_xor_sync(0xffffffffu, ls0, 2);
    ls1 += __shfl_xor_sync(0xffffffffu, ls1, 1);
    ls1 += __shfl_xor_sync(0xffffffffu, ls1, 2);
    l[0] = l[0] * cs0 + ls0; m[0] = mn0;
    l[1] = l[1] * cs1 + ls1; m[1] = mn1;
#pragma unroll
    for (int nd = 0; nd < 8; nd++) {
        oacc[nd][0] *= cs0; oacc[nd][1] *= cs0;
        oacc[nd][2] *= cs1; oacc[nd][3] *= cs1;
    }

    int jrow = ((g & 1) << 3) + w;
    int dcol = (g >> 1) * 16;
#pragma unroll
    for (int kk = 0; kk < NKK; kk++) {
        if (((skipmask >> (2 * kk)) & 3u) == 3u) continue;
        uint32_t pa[4] = { pp[2*kk][0], pp[2*kk][1], pp[2*kk+1][0], pp[2*kk+1][1] };
#pragma unroll
        for (int gv = 0; gv < 2; gv++) {
            uint32_t vh4[2][4];
#pragma unroll
            for (int u = 0; u < 2; u++) {
                int nd2 = gv * 2 + u;
                ldmx4t(vh4[u], vst + (colbase + kk * 16 + jrow) * 144 + nd2 * 32 + dcol);
            }
#pragma unroll
            for (int u = 0; u < 2; u++) {
                int nd2 = gv * 2 + u;
                mma16816(oacc[nd2 * 2],     pa, vh4[u]);
                mma16816(oacc[nd2 * 2 + 1], pa, vh4[u] + 2);
            }
        }
    }
}

__global__ __launch_bounds__(512, 1)
void attn_mma()
{
    extern __shared__ __align__(16) char sm[];
    uint32_t smb = smem_u32(sm);
    int tid = threadIdx.x, lane = tid & 31, wid = tid >> 5;
    int rg = wid >> 1, ch2 = wid & 1;
    int qb = (gridDim.x - 1) - blockIdx.x;       // heavy-first scheduling
    int bh = blockIdx.y;

    auto stage_rows = [&](uint32_t dst, const __half* src, int nrows) {
        for (int c = tid; c < nrows * 8; c += 512) {
            int row = c >> 3, ch = c & 7;
            cpasync16(dst + row * 144 + ch * 16, src + (size_t)row * HD + ch * 8);
        }
    };
    size_t hb = (size_t)bh * TSEQ * HD;
    const __half* Qg = g_q16 + hb + (size_t)qb * 128 * HD;

    float oacc[8][4];
#pragma unroll
    for (int nd = 0; nd < 8; nd++)
#pragma unroll
        for (int q = 0; q < 4; q++) oacc[nd][q] = 0.f;
    float m[2] = { -1e30f, -1e30f }, l[2] = { 0.f, 0.f };
    int i0 = qb * 128 + rg * 16 + (lane >> 2);

    if (qb >= 3) {
        stage_rows(smb + SMQ, Qg, 128);
        stage_rows(smb + SB1,         g_k16 + hb + (size_t)(qb - 1) * 128 * HD, 128);
        stage_rows(smb + SB1 + 18432, g_v16 + hb + (size_t)(qb - 1) * 128 * HD, 128);
        CP_COMMIT();
        stage_rows(smb + SB0,         g_k16 + hb + (size_t)(qb - 2) * 128 * HD, 128);
        stage_rows(smb + SB0 + 18432, g_v16 + hb + (size_t)(qb - 2) * 128 * HD, 128);
        CP_COMMIT();
        stage_rows(smb + SB2,         g_k16 + hb + (size_t)qb * 128 * HD, 128);
        stage_rows(smb + SB2 + 18432, g_v16 + hb + (size_t)qb * 128 * HD, 128);
        stage_rows(smb + SBG,        g_k16 + hb, 16);
        stage_rows(smb + SBG + 2304, g_v16 + hb, 16);
        CP_COMMIT();

        CP_WAIT2(); __syncthreads();
        dense_block<8, 0>(smb, smb + SB1, smb + SB1 + 18432, lane, rg, ch2 * 64,
                          i0, (qb - 1) * 128 + ch2 * 64, oacc, m, l);
        CP_WAIT0(); __syncthreads();
        dense_block<8, 1>(smb, smb + SB0, smb + SB0 + 18432, lane, rg, ch2 * 64,
                          i0, (qb - 2) * 128 + ch2 * 64, oacc, m, l);
        dense_block<8, 2>(smb, smb + SB2, smb + SB2 + 18432, lane, rg, ch2 * 64,
                          i0, qb * 128 + ch2 * 64, oacc, m, l);
        if (ch2 == 0)
            dense_block<2, 0>(smb, smb + SBG, smb + SBG + 2304, lane, rg, 0,
                              i0, 0, oacc, m, l);
    } else {
        stage_rows(smb + SMQ, Qg, 128);
        stage_rows(smb + SB0, g_k16 + hb, 128);
        stage_rows(smb + SB0 + 18432, g_v16 + hb, 128);
        CP_COMMIT();
        if (qb >= 1) {
            stage_rows(smb + SB1, g_k16 + hb + (size_t)128 * HD, 128);
            stage_rows(smb + SB1 + 18432, g_v16 + hb + (size_t)128 * HD, 128);
        }
        CP_COMMIT();
        if (qb >= 2) {
            stage_rows(smb + SB2, g_k16 + hb + (size_t)256 * HD, 128);
            stage_rows(smb + SB2 + 18432, g_v16 + hb + (size_t)256 * HD, 128);
        }
        CP_COMMIT();
        CP_WAIT0(); __syncthreads();
        uint32_t bufs[3] = { smb + SB0, smb + SB1, smb + SB2 };
        for (int kb = 0; kb <= qb; kb++)
            dense_block<8, 3>(smb, bufs[kb], bufs[kb] + 18432, lane, rg, ch2 * 64,
                              i0, kb * 128 + ch2 * 64, oacc, m, l);
    }

    // strided diagonals (kb 0..qb-3); warp pair splits even/odd
    int nkb = qb - 2;
    float* Sst = (float*)(sm + SST);
    if (nkb > 0) {
        int part = lane & 3;
        for (int pass = 0; pass < 2; pass++) {
            int rloc = rg * 16 + pass * 8 + (lane >> 2);
            // hoist Q (kb-invariant)
            uint32_t q4h[2][4];
            uint32_t qb0 = smb + SMQ + rloc * 144 + part * 32;
#pragma unroll
            for (int seg = 0; seg < 2; seg++)
                asm volatile("ld.shared.v4.b32 {%0,%1,%2,%3}, [%4];"
                    : "=r"(q4h[seg][0]), "=r"(q4h[seg][1]),
                      "=r"(q4h[seg][2]), "=r"(q4h[seg][3])
                    : "r"(qb0 + seg * 16));

            auto score_one = [&](int kb) -> float {
                if (kb == 0 && rloc < 16) return -1e30f;
                int j = kb * 128 + rloc;
                size_t kbase = hb + (size_t)j * HD + part * 16;
                uint4 k4a = *(const uint4*)&g_k16[kbase];
                uint4 k4b = *(const uint4*)&g_k16[kbase + 8];
                const uint32_t* kpa = (const uint32_t*)&k4a;
                const uint32_t* kpb = (const uint32_t*)&k4b;
                float sum = 0.f;
#pragma unroll
                for (int u = 0; u < 4; u++) {
                    float2 qf = h2f2(q4h[0][u]), kf = h2f2(kpa[u]);
                    sum += qf.x * kf.x + qf.y * kf.y;
                }
#pragma unroll
                for (int u = 0; u < 4; u++) {
                    float2 qf = h2f2(q4h[1][u]), kf = h2f2(kpb[u]);
                    sum += qf.x * kf.x + qf.y * kf.y;
                }
                sum += __shfl_xor_sync(0xffffffffu, sum, 1);
                sum += __shfl_xor_sync(0xffffffffu, sum, 2);
                return sum * SCALE2;
            };

            int kb = ch2;
            for (; kb + 2 < nkb; kb += 4) {      // 2 strided iterations batched
                float s0 = score_one(kb);
                float s1 = score_one(kb + 2);
                if (part == 0) {
                    Sst[rloc * 33 + kb] = s0;
                    Sst[rloc * 33 + kb + 2] = s1;
                }
            }
            for (; kb < nkb; kb += 2) {
                float s0 = score_one(kb);
                if (part == 0) Sst[rloc * 33 + kb] = s0;
            }
        }
        __syncwarp();

#pragma unroll
        for (int h = 0; h < 2; h++) {
            int r = rg * 16 + (lane >> 2) + h * 8;
            float mo = m[h], mx = mo;
            for (int kb = ch2; kb < nkb; kb += 2)
                mx = fmaxf(mx, Sst[r * 33 + kb]);
            mx = fmaxf(mx, -1e28f);
            float cs = ex2(mo - mx);
            float ls = 0.f;
#pragma unroll
            for (int nd = 0; nd < 8; nd++) {
                oacc[nd][h * 2 + 0] *= cs;
                oacc[nd][h * 2 + 1] *= cs;
            }
            for (int kb = ch2; kb < nkb; kb += 2) {
                float p = ex2(Sst[r * 33 + kb] - mx);
                ls += p;
                if (p > 0.f) {
                    int j = kb * 128 + r;
                    size_t vb = hb + (size_t)j * HD;
#pragma unroll
                    for (int nd = 0; nd < 8; nd++) {
                        int d0 = nd * 8 + (lane & 3) * 2;
                        float2 vf = h2f2(*(const uint32_t*)&g_v16[vb + d0]);
                        oacc[nd][h * 2 + 0] += p * vf.x;
                        oacc[nd][h * 2 + 1] += p * vf.y;
                    }
                }
            }
            m[h] = mx;
            l[h] = l[h] * cs + ls;
        }
    }

    // pairwise split-softmax merge, then epilogue
    __syncthreads();
    {
        char* mb = sm + SMRG + wid * MERGE_B;
#pragma unroll
        for (int h = 0; h < 2; h++) {
            int row = (lane >> 2) + h * 8;
#pragma unroll
            for (int nd = 0; nd < 8; nd++) {
                int col = nd * 8 + (lane & 3) * 2;
                *(float2*)(mb + (row * 64 + col) * 4) =
                    make_float2(oacc[nd][h * 2], oacc[nd][h * 2 + 1]);
            }
            if ((lane & 3) == 0)
                *(float2*)(mb + 4096 + row * 8) = make_float2(m[h], l[h]);
        }
    }
    __syncthreads();
    if (ch2 == 0) {
        char* pb = sm + SMRG + (wid + 1) * MERGE_B;
        int b = bh >> 4, head = bh & 15;
#pragma unroll
        for (int h = 0; h < 2; h++) {
            int row = (lane >> 2) + h * 8;
            float2 ml = *(float2*)(pb + 4096 + row * 8);
            float mx = fmaxf(m[h], ml.x);
            float f0 = ex2(m[h] - mx), f1 = ex2(ml.x - mx);
            float L = l[h] * f0 + ml.y * f1;
            float inv = 1.f / L;
            int i = qb * 128 + rg * 16 + row;
            size_t row_off = ((size_t)(b * TSEQ + i)) * CEMB + head * HD;
#pragma unroll
            for (int nd = 0; nd < 8; nd++) {
                int col = nd * 8 + (lane & 3) * 2;
                float2 o1 = *(float2*)(pb + (row * 64 + col) * 4);
                float y0 = (oacc[nd][h * 2 + 0] * f0 + o1.x * f1) * inv;
                float y1 = (oacc[nd][h * 2 + 1] * f0 + o1.y * f1) * inv;
                *(uint32_t*)&g_y16[row_off + col] = packh(y0, y1);
            }
        }
    }
}

// ---------------- launch -------------------------------------------------------
extern "C" void kernel_launch(void* const* d_in, const int* in_sizes, int n_in,
                              void* d_out, int out_size)
{
    const float* x      = (const float*)d_in[0];
    const float* w_qkv  = (const float*)d_in[1];
    const float* b_qkv  = (const float*)d_in[2];
    const float* w_proj = (const float*)d_in[3];
    const float* b_proj = (const float*)d_in[4];
    float* out = (float*)d_out;

    cudaFuncSetAttribute(gemm_mma<0>,
                         cudaFuncAttributeMaxDynamicSharedMemorySize, GSMEM);
    cudaFuncSetAttribute(gemm_mma<1>,
                         cudaFuncAttributeMaxDynamicSharedMemorySize, GSMEM);
    cudaFuncSetAttribute(attn_mma,
                         cudaFuncAttributeMaxDynamicSharedMemorySize, ATTN_SM);

    int n_x = MROWS * CEMB;
    conv_f16_x<<<n_x / 4 / 256, 256>>>(x, n_x);
    conv_f16_T<0><<<dim3(3 * CEMB / 32, CEMB / 32), 256>>>(w_qkv, CEMB, 3 * CEMB);
    conv_f16_T<1><<<dim3(CEMB / 32, CEMB / 32), 256>>>(w_proj, CEMB, CEMB);

    gemm_mma<0><<<dim3(3 * CEMB / 128, MROWS / 128), 256, GSMEM>>>(b_qkv, nullptr);
    attn_mma<<<dim3(TSEQ / 128, BATCH * NH), 512, ATTN_SM>>>();
    gemm_mma<1><<<dim3(CEMB / 128, MROWS / 128), 256, GSMEM>>>(b_proj, out);
}

// round 11
// speedup vs baseline: 2.4537x; 1.0049x over previous
#include <cuda_runtime.h>
#include <cuda_fp16.h>
#include <cstdint>
#include <math.h>

#define BATCH 2
#define TSEQ  4096
#define NH    16
#define HD    64
#define CEMB  1024
#define MROWS (BATCH*TSEQ)          // 8192
#define SCALE2 0.1803368801111204f  // (1/8) * log2(e)

// ---------------- scratch (fp16 operands) --------------------------------------
__device__ __half g_x16[(size_t)MROWS*CEMB];
__device__ __half g_y16[(size_t)MROWS*CEMB];
__device__ __half g_wq16[(size_t)3*CEMB*CEMB];   // [N,K] K-major
__device__ __half g_wp16[(size_t)CEMB*CEMB];
__device__ __half g_q16[(size_t)BATCH*NH*TSEQ*HD];
__device__ __half g_k16[(size_t)BATCH*NH*TSEQ*HD];
__device__ __half g_v16[(size_t)BATCH*NH*TSEQ*HD];

// ---------------- PTX helpers --------------------------------------------------
__device__ __forceinline__ uint32_t smem_u32(const void* p) {
    uint32_t a;
    asm("{ .reg .u64 t; cvta.to.shared.u64 t, %1; cvt.u32.u64 %0, t; }"
        : "=r"(a) : "l"(p));
    return a;
}
__device__ __forceinline__ void cpasync16(uint32_t saddr, const void* g) {
    asm volatile("cp.async.cg.shared.global [%0], [%1], 16;"
                 :: "r"(saddr), "l"(g) : "memory");
}
#define CP_COMMIT() asm volatile("cp.async.commit_group;" ::: "memory")
#define CP_WAIT2()  asm volatile("cp.async.wait_group 2;" ::: "memory")
#define CP_WAIT1()  asm volatile("cp.async.wait_group 1;" ::: "memory")
#define CP_WAIT0()  asm volatile("cp.async.wait_group 0;" ::: "memory")

__device__ __forceinline__ void ldmx4(uint32_t* r, uint32_t addr) {
    asm volatile("ldmatrix.sync.aligned.m8n8.x4.shared.b16 {%0,%1,%2,%3}, [%4];"
        : "=r"(r[0]), "=r"(r[1]), "=r"(r[2]), "=r"(r[3]) : "r"(addr));
}
__device__ __forceinline__ void ldmx2(uint32_t* r, uint32_t addr) {
    asm volatile("ldmatrix.sync.aligned.m8n8.x2.shared.b16 {%0,%1}, [%2];"
        : "=r"(r[0]), "=r"(r[1]) : "r"(addr));
}
__device__ __forceinline__ void ldmx4t(uint32_t* r, uint32_t addr) {
    asm volatile("ldmatrix.sync.aligned.m8n8.x4.trans.shared.b16 {%0,%1,%2,%3}, [%4];"
        : "=r"(r[0]), "=r"(r[1]), "=r"(r[2]), "=r"(r[3]) : "r"(addr));
}
__device__ __forceinline__ void mma16816(float* d, const uint32_t* a,
                                         const uint32_t* b) {
    asm volatile(
        "mma.sync.aligned.m16n8k16.row.col.f32.f16.f16.f32 "
        "{%0,%1,%2,%3}, {%4,%5,%6,%7}, {%8,%9}, {%0,%1,%2,%3};"
        : "+f"(d[0]), "+f"(d[1]), "+f"(d[2]), "+f"(d[3])
        : "r"(a[0]), "r"(a[1]), "r"(a[2]), "r"(a[3]), "r"(b[0]), "r"(b[1]));
}

__device__ __forceinline__ float ex2(float x) {
    float r;
    asm("ex2.approx.ftz.f32 %0, %1;" : "=f"(r) : "f"(x));
    return r;
}
__device__ __forceinline__ uint32_t ex2h2(uint32_t x) {
    uint32_t r;
    asm("ex2.approx.f16x2 %0, %1;" : "=r"(r) : "r"(x));
    return r;
}
__device__ __forceinline__ float2 h2f2(uint32_t u) {
    __half2 h = *(__half2*)&u;
    return __half22float2(h);
}
__device__ __forceinline__ uint32_t packh(float x, float y) {
    __half2 t = __floats2half2_rn(x, y);
    return *(uint32_t*)&t;
}

// ---------------- conversion kernels -------------------------------------------
__global__ void conv_f16_x(const float* __restrict__ src, int n) {
    int i = (blockIdx.x * 256 + threadIdx.x) * 4;
    if (i < n) {
        float4 v = *(const float4*)&src[i];
        uint2 p;
        p.x = packh(v.x, v.y);
        p.y = packh(v.z, v.w);
        *(uint2*)&g_x16[i] = p;
    }
}
template <int W>
__global__ void conv_f16_T(const float* __restrict__ w, int K, int N) {
    __shared__ float t[32][33];
    __half* dT = (W == 0) ? g_wq16 : g_wp16;
    int n0 = blockIdx.x * 32, k0 = blockIdx.y * 32;
    int tx = threadIdx.x & 31, ty = threadIdx.x >> 5;
    for (int r = ty; r < 32; r += 8)
        t[r][tx] = w[(size_t)(k0 + r) * N + n0 + tx];
    __syncthreads();
    for (int r = ty; r < 32; r += 8)
        dT[(size_t)(n0 + r) * K + k0 + tx] = __float2half_rn(t[tx][r]);
}

// ---------------- fp16 GEMM, 3-stage cp.async, 2 CTAs/SM -----------------------
#define BK    64
#define ROWB  144
#define MATB  (128*ROWB)            // 18432
#define STAGEB (2*MATB)             // 36864
#define GSMEM (3*STAGEB)            // 110592

template <int MODE>
__global__ __launch_bounds__(256, 2)
void gemm_mma(const float* __restrict__ bias, float* __restrict__ out)
{
    extern __shared__ __align__(16) char sm[];
    uint32_t smb = smem_u32(sm);

    const __half* A16 = (MODE == 0) ? g_x16 : g_y16;
    const __half* B16 = (MODE == 0) ? g_wq16 : g_wp16;

    int tid = threadIdx.x;
    int wid = tid >> 5, lane = tid & 31;
    int wm = wid >> 2, wn = wid & 3;
    int mBase = blockIdx.y * 128, nBase = blockIdx.x * 128;

    float acc[4][4][4];
#pragma unroll
    for (int mi = 0; mi < 4; mi++)
#pragma unroll
        for (int ni = 0; ni < 4; ni++)
#pragma unroll
            for (int q = 0; q < 4; q++) acc[mi][ni][q] = 0.f;

    auto load_stage = [&](int st, int kt) {
        int k0 = kt * BK;
        uint32_t sb = smb + st * STAGEB;
#pragma unroll
        for (int c = tid; c < 1024; c += 256) {
            int row = c >> 3, ch = c & 7;
            cpasync16(sb + row * ROWB + ch * 16,
                      A16 + (size_t)(mBase + row) * CEMB + k0 + ch * 8);
        }
#pragma unroll
        for (int c = tid; c < 1024; c += 256) {
            int row = c >> 3, ch = c & 7;
            cpasync16(sb + MATB + row * ROWB + ch * 16,
                      B16 + (size_t)(nBase + row) * CEMB + k0 + ch * 8);
        }
    };

    int g = lane >> 3, w = lane & 7;
    uint32_t a_row = (wm * 64 + ((g & 1) << 3) + w) * ROWB;
    uint32_t b_row = (wn * 32 + w) * ROWB;
    uint32_t ka_off = ((g >> 1) << 3) * 2;
    uint32_t kb_off = ((g & 1) << 3) * 2;

    load_stage(0, 0); CP_COMMIT();
    load_stage(1, 1); CP_COMMIT();

    for (int kt = 0; kt < 16; kt++) {
        if (kt < 15) CP_WAIT1(); else CP_WAIT0();
        __syncthreads();
        if (kt + 2 < 16) { load_stage((kt + 2) % 3, kt + 2); CP_COMMIT(); }

        uint32_t bA = smb + (kt % 3) * STAGEB;
        uint32_t bB = bA + MATB;

#pragma unroll
        for (int ks = 0; ks < 4; ks++) {
            uint32_t ka = ks * 32 + ka_off;
            uint32_t kb = ks * 32 + kb_off;
            uint32_t ah[4][4], bh[4][2];
#pragma unroll
            for (int mi = 0; mi < 4; mi++)
                ldmx4(ah[mi], bA + a_row + mi * 16 * ROWB + ka);
#pragma unroll
            for (int ni = 0; ni < 4; ni++)
                ldmx2(bh[ni], bB + b_row + ni * 8 * ROWB + kb);
#pragma unroll
            for (int mi = 0; mi < 4; mi++)
#pragma unroll
                for (int ni = 0; ni < 4; ni++)
                    mma16816(acc[mi][ni], ah[mi], bh[ni]);
        }
        __syncthreads();
    }

    int r_in = lane >> 2, c_in = (lane & 3) * 2;
#pragma unroll
    for (int mi = 0; mi < 4; mi++) {
#pragma unroll
        for (int half = 0; half < 2; half++) {
            int m = mBase + wm * 64 + mi * 16 + r_in + half * 8;
#pragma unroll
            for (int ni = 0; ni < 4; ni++) {
                int n = nBase + wn * 32 + ni * 8 + c_in;
                float v0 = acc[mi][ni][half * 2 + 0] + bias[n];
                float v1 = acc[mi][ni][half * 2 + 1] + bias[n + 1];
                if (MODE == 0) {
                    int b = m >> 12, t = m & 4095;
                    int sect = n >> 10, cc = n & 1023;
                    int head = cc >> 6, d0 = cc & 63;
                    size_t off = (((size_t)(b * NH + head)) * TSEQ + t) * HD + d0;
                    __half* dst = (sect == 0) ? g_q16 : (sect == 1) ? g_k16 : g_v16;
                    *(uint32_t*)&dst[off] = packh(v0, v1);
                } else {
                    *(float2*)&out[(size_t)m * CEMB + n] = make_float2(v0, v1);
                }
            }
        }
    }
}

// ---------------- fp16 HMMA block-sparse flash attention -----------------------
#define SMQ    0
#define SB0    18432
#define SB1    55296
#define SB2    92160
#define SBG    129024
#define SLAB   18432                        // strided slabs overlay SB0.. after barrier
#define SLABW  12288                        // 3 stages x 4096 (K 2048 + V 2048)
#define SMRG   18432                        // merge slabs overlay after barrier
#define MERGE_B 4352
#define ATTN_SM (SLAB + 16*SLABW)           // 215040

// MODE: 0 = fully valid, 1 = upper (diff<=256), 2 = lower (causal), 3 = general
template <int NNI, int MODE>
__device__ __forceinline__ void dense_block(
    uint32_t smb, uint32_t kst, uint32_t vst, int lane, int rg, int colbase,
    int i0, int jb, float (&oacc)[8][4], float (&m)[2], float (&l)[2])
{
    const int NKK = NNI / 2;
    int g = lane >> 3, w = lane & 7;
    uint32_t arow = smb + SMQ + (rg * 16 + ((g & 1) << 3) + w) * 144;
    uint32_t ka = (g >> 1) * 16;
    uint32_t kboff = (g & 1) * 16;
    int r0 = rg * 16;

    unsigned skipmask = 0;
    if (MODE == 1) {
#pragma unroll
        for (int ni = 0; ni < NNI; ni++)
            if (colbase + ni * 8 + 7 < r0) skipmask |= 1u << ni;
    } else if (MODE == 2) {
#pragma unroll
        for (int ni = 0; ni < NNI; ni++)
            if (colbase + ni * 8 > r0 + 15) skipmask |= 1u << ni;
    }

    float sacc[NNI][4];
#pragma unroll
    for (int ni = 0; ni < NNI; ni++)
#pragma unroll
        for (int q = 0; q < 4; q++) sacc[ni][q] = 0.f;

#pragma unroll
    for (int ks = 0; ks < 4; ks++) {
        uint32_t q4[4];
        ldmx4(q4, arow + ks * 32 + ka);
#pragma unroll
        for (int ni = 0; ni < NNI; ni++) {
            if ((skipmask >> ni) & 1) continue;
            uint32_t kb2[2];
            ldmx2(kb2, kst + (colbase + ni * 8 + w) * 144 + kboff + ks * 32);
            mma16816(sacc[ni], q4, kb2);
        }
    }

    int c0 = (lane & 3) * 2;
    float mb0 = -1e30f, mb1 = -1e30f;
#pragma unroll
    for (int ni = 0; ni < NNI; ni++) {
        if ((skipmask >> ni) & 1) continue;
        int jB = jb + ni * 8 + c0;
#pragma unroll
        for (int q = 0; q < 4; q++) {
            int jj = jB + (q & 1);
            int ii = (q < 2) ? i0 : i0 + 8;
            bool ok;
            if (MODE == 0) ok = true;
            else if (MODE == 1) ok = (ii - jj) <= 256;
            else if (MODE == 2) ok = jj <= ii;
            else {
                int diff = ii - jj;
                ok = diff >= 0 && (diff < 256 || (diff & 127) == 0 || jj < 16);
            }
            sacc[ni][q] = ok ? sacc[ni][q] * SCALE2 : -1e30f;
        }
        mb0 = fmaxf(mb0, fmaxf(sacc[ni][0], sacc[ni][1]));
        mb1 = fmaxf(mb1, fmaxf(sacc[ni][2], sacc[ni][3]));
    }
    mb0 = fmaxf(mb0, __shfl_xor_sync(0xffffffffu, mb0, 1));
    mb0 = fmaxf(mb0, __shfl_xor_sync(0xffffffffu, mb0, 2));
    mb1 = fmaxf(mb1, __shfl_xor_sync(0xffffffffu, mb1, 1));
    mb1 = fmaxf(mb1, __shfl_xor_sync(0xffffffffu, mb1, 2));

    float mn0 = fmaxf(fmaxf(m[0], mb0), -1e28f);
    float mn1 = fmaxf(fmaxf(m[1], mb1), -1e28f);
    float cs0 = ex2(m[0] - mn0), cs1 = ex2(m[1] - mn1);

    uint32_t pp[NNI][2];
    float ls0 = 0.f, ls1 = 0.f;
#pragma unroll
    for (int ni = 0; ni < NNI; ni++) {
        if ((skipmask >> ni) & 1) { pp[ni][0] = 0u; pp[ni][1] = 0u; continue; }
        uint32_t a0 = packh(sacc[ni][0] - mn0, sacc[ni][1] - mn0);
        uint32_t a1 = packh(sacc[ni][2] - mn1, sacc[ni][3] - mn1);
        uint32_t p0 = ex2h2(a0), p1 = ex2h2(a1);
        pp[ni][0] = p0; pp[ni][1] = p1;
        float2 f0 = h2f2(p0), f1 = h2f2(p1);
        ls0 += f0.x + f0.y; ls1 += f1.x + f1.y;
    }
    ls0 += __shfl_xor_sync(0xffffffffu, ls0, 1);
    ls0 += __shfl_xor_sync(0xffffffffu, ls0, 2);
    ls1 += __shfl_xor_sync(0xffffffffu, ls1, 1);
    ls1 += __shfl_xor_sync(0xffffffffu, ls1, 2);
    l[0] = l[0] * cs0 + ls0; m[0] = mn0;
    l[1] = l[1] * cs1 + ls1; m[1] = mn1;
#pragma unroll
    for (int nd = 0; nd < 8; nd++) {
        oacc[nd][0] *= cs0; oacc[nd][1] *= cs0;
        oacc[nd][2] *= cs1; oacc[nd][3] *= cs1;
    }

    int jrow = ((g & 1) << 3) + w;
    int dcol = (g >> 1) * 16;
#pragma unroll
    for (int kk = 0; kk < NKK; kk++) {
        if (((skipmask >> (2 * kk)) & 3u) == 3u) continue;
        uint32_t pa[4] = { pp[2*kk][0], pp[2*kk][1], pp[2*kk+1][0], pp[2*kk+1][1] };
#pragma unroll
        for (int gv = 0; gv < 2; gv++) {
            uint32_t vh4[2][4];
#pragma unroll
            for (int u = 0; u < 2; u++) {
                int nd2 = gv * 2 + u;
                ldmx4t(vh4[u], vst + (colbase + kk * 16 + jrow) * 144 + nd2 * 32 + dcol);
            }
#pragma unroll
            for (int u = 0; u < 2; u++) {
                int nd2 = gv * 2 + u;
                mma16816(oacc[nd2 * 2],     pa, vh4[u]);
                mma16816(oacc[nd2 * 2 + 1], pa, vh4[u] + 2);
            }
        }
    }
}

__global__ __launch_bounds__(512, 1)
void attn_mma()
{
    extern __shared__ __align__(16) char sm[];
    uint32_t smb = smem_u32(sm);
    int tid = threadIdx.x, lane = tid & 31, wid = tid >> 5;
    int rg = wid >> 1, ch2 = wid & 1;
    int qb = (gridDim.x - 1) - blockIdx.x;       // heavy-first scheduling
    int bh = blockIdx.y;

    auto stage_rows = [&](uint32_t dst, const __half* src, int nrows) {
        for (int c = tid; c < nrows * 8; c += 512) {
            int row = c >> 3, ch = c & 7;
            cpasync16(dst + row * 144 + ch * 16, src + (size_t)row * HD + ch * 8);
        }
    };
    size_t hb = (size_t)bh * TSEQ * HD;
    const __half* Qg = g_q16 + hb + (size_t)qb * 128 * HD;

    float oacc[8][4];
#pragma unroll
    for (int nd = 0; nd < 8; nd++)
#pragma unroll
        for (int q = 0; q < 4; q++) oacc[nd][q] = 0.f;
    float m[2] = { -1e30f, -1e30f }, l[2] = { 0.f, 0.f };
    int i0 = qb * 128 + rg * 16 + (lane >> 2);

    if (qb >= 3) {
        stage_rows(smb + SMQ, Qg, 128);
        stage_rows(smb + SB1,         g_k16 + hb + (size_t)(qb - 1) * 128 * HD, 128);
        stage_rows(smb + SB1 + 18432, g_v16 + hb + (size_t)(qb - 1) * 128 * HD, 128);
        CP_COMMIT();
        stage_rows(smb + SB0,         g_k16 + hb + (size_t)(qb - 2) * 128 * HD, 128);
        stage_rows(smb + SB0 + 18432, g_v16 + hb + (size_t)(qb - 2) * 128 * HD, 128);
        CP_COMMIT();
        stage_rows(smb + SB2,         g_k16 + hb + (size_t)qb * 128 * HD, 128);
        stage_rows(smb + SB2 + 18432, g_v16 + hb + (size_t)qb * 128 * HD, 128);
        stage_rows(smb + SBG,        g_k16 + hb, 16);
        stage_rows(smb + SBG + 2304, g_v16 + hb, 16);
        CP_COMMIT();

        CP_WAIT2(); __syncthreads();
        dense_block<8, 0>(smb, smb + SB1, smb + SB1 + 18432, lane, rg, ch2 * 64,
                          i0, (qb - 1) * 128 + ch2 * 64, oacc, m, l);
        CP_WAIT0(); __syncthreads();
        dense_block<8, 1>(smb, smb + SB0, smb + SB0 + 18432, lane, rg, ch2 * 64,
                          i0, (qb - 2) * 128 + ch2 * 64, oacc, m, l);
        dense_block<8, 2>(smb, smb + SB2, smb + SB2 + 18432, lane, rg, ch2 * 64,
                          i0, qb * 128 + ch2 * 64, oacc, m, l);
        if (ch2 == 0)
            dense_block<2, 0>(smb, smb + SBG, smb + SBG + 2304, lane, rg, 0,
                              i0, 0, oacc, m, l);
    } else {
        stage_rows(smb + SMQ, Qg, 128);
        stage_rows(smb + SB0, g_k16 + hb, 128);
        stage_rows(smb + SB0 + 18432, g_v16 + hb, 128);
        CP_COMMIT();
        if (qb >= 1) {
            stage_rows(smb + SB1, g_k16 + hb + (size_t)128 * HD, 128);
            stage_rows(smb + SB1 + 18432, g_v16 + hb + (size_t)128 * HD, 128);
        }
        CP_COMMIT();
        if (qb >= 2) {
            stage_rows(smb + SB2, g_k16 + hb + (size_t)256 * HD, 128);
            stage_rows(smb + SB2 + 18432, g_v16 + hb + (size_t)256 * HD, 128);
        }
        CP_COMMIT();
        CP_WAIT0(); __syncthreads();
        uint32_t bufs[3] = { smb + SB0, smb + SB1, smb + SB2 };
        for (int kb = 0; kb <= qb; kb++)
            dense_block<8, 3>(smb, bufs[kb], bufs[kb] + 18432, lane, rg, ch2 * 64,
                              i0, kb * 128 + ch2 * 64, oacc, m, l);
    }

    // ---------- strided diagonals: single-pass, per-warp cp.async pipeline -----
    int nkb = qb - 2;
    if (nkb > 0) {
        __syncthreads();                       // dense buffers dead; slabs overlay
        uint32_t slab = smb + SLAB + wid * SLABW;
        int part = lane & 3, qr = lane >> 2;

        auto stage_kb = [&](int slot, int kb) {
            const __half* Ksrc = g_k16 + hb + ((size_t)kb * 128 + rg * 16) * HD;
            const __half* Vsrc = g_v16 + hb + ((size_t)kb * 128 + rg * 16) * HD;
            uint32_t base = slab + slot * 4096;
#pragma unroll
            for (int c = lane; c < 128; c += 32) {
                int row = c >> 3, ch = c & 7;
                cpasync16(base + row * 128 + ch * 16,
                          Ksrc + (size_t)row * HD + ch * 8);
                cpasync16(base + 2048 + row * 128 + ch * 16,
                          Vsrc + (size_t)row * HD + ch * 8);
            }
            CP_COMMIT();
        };

        int nexts = ch2;
#pragma unroll
        for (int s = 0; s < 3; s++) {
            if (nexts < nkb) { stage_kb(s, nexts); nexts += 2; }
        }

        int it = 0;
        for (int kb = ch2; kb < nkb; kb += 2, it++) {
            int ahead = (nexts - kb) >> 1;     // stages in flight incl. current
            if (ahead >= 3) CP_WAIT2();
            else if (ahead == 2) CP_WAIT1();
            else CP_WAIT0();
            __syncwarp();

            uint32_t st = slab + (it % 3) * 4096;
#pragma unroll
            for (int h = 0; h < 2; h++) {
                int lr = qr + h * 8;
                int rloc = rg * 16 + lr;
                float s;
                if (kb == 0 && rloc < 16) {
                    s = -1e30f;
                } else {
                    uint32_t kaddr = st + lr * 128 + part * 32;
                    uint32_t qaddr = smb + SMQ + rloc * 144 + part * 32;
                    float sum = 0.f;
#pragma unroll
                    for (int seg = 0; seg < 2; seg++) {
                        uint32_t k4[4], q4[4];
                        asm volatile("ld.shared.v4.b32 {%0,%1,%2,%3}, [%4];"
                            : "=r"(k4[0]), "=r"(k4[1]), "=r"(k4[2]), "=r"(k4[3])
                            : "r"(kaddr + seg * 16));
                        asm volatile("ld.shared.v4.b32 {%0,%1,%2,%3}, [%4];"
                            : "=r"(q4[0]), "=r"(q4[1]), "=r"(q4[2]), "=r"(q4[3])
                            : "r"(qaddr + seg * 16));
#pragma unroll
                        for (int u = 0; u < 4; u++) {
                            float2 qf = h2f2(q4[u]), kf = h2f2(k4[u]);
                            sum += qf.x * kf.x + qf.y * kf.y;
                        }
                    }
                    sum += __shfl_xor_sync(0xffffffffu, sum, 1);
                    sum += __shfl_xor_sync(0xffffffffu, sum, 2);
                    s = sum * SCALE2;
                }
                float mold = m[h];
                float mx = fmaxf(fmaxf(mold, s), -1e28f);
                float p = ex2(s - mx);
                if (__any_sync(0xffffffffu, mx > mold)) {
                    float cs = ex2(mold - mx);
                    l[h] = l[h] * cs + p;
                    m[h] = mx;
#pragma unroll
                    for (int nd = 0; nd < 8; nd++) {
                        oacc[nd][h * 2 + 0] *= cs;
                        oacc[nd][h * 2 + 1] *= cs;
                    }
                } else {
                    l[h] += p;
                }
                uint32_t vaddr = st + 2048 + lr * 128 + part * 4;
#pragma unroll
                for (int nd = 0; nd < 8; nd++) {
                    uint32_t vv;
                    asm volatile("ld.shared.b32 %0, [%1];"
                        : "=r"(vv) : "r"(vaddr + nd * 16));
                    float2 vf = h2f2(vv);
                    oacc[nd][h * 2 + 0] += p * vf.x;
                    oacc[nd][h * 2 + 1] += p * vf.y;
                }
            }

            if (nexts < nkb) {
                __syncwarp();                  // all lanes done reading slot
                stage_kb(it % 3, nexts);       // reuse just-freed slot
                nexts += 2;
            }
        }
    }

    // pairwise split-softmax merge, then epilogue
    __syncthreads();
    {
        char* mb = sm + SMRG + wid * MERGE_B;
#pragma unroll
        for (int h = 0; h < 2; h++) {
            int row = (lane >> 2) + h * 8;
#pragma unroll
            for (int nd = 0; nd < 8; nd++) {
                int col = nd * 8 + (lane & 3) * 2;
                *(float2*)(mb + (row * 64 + col) * 4) =
                    make_float2(oacc[nd][h * 2], oacc[nd][h * 2 + 1]);
            }
            if ((lane & 3) == 0)
                *(float2*)(mb + 4096 + row * 8) = make_float2(m[h], l[h]);
        }
    }
    __syncthreads();
    if (ch2 == 0) {
        char* pb = sm + SMRG + (wid + 1) * MERGE_B;
        int b = bh >> 4, head = bh & 15;
#pragma unroll
        for (int h = 0; h < 2; h++) {
            int row = (lane >> 2) + h * 8;
            float2 ml = *(float2*)(pb + 4096 + row * 8);
            float mx = fmaxf(m[h], ml.x);
            float f0 = ex2(m[h] - mx), f1 = ex2(ml.x - mx);
            float L = l[h] * f0 + ml.y * f1;
            float inv = 1.f / L;
            int i = qb * 128 + rg * 16 + row;
            size_t row_off = ((size_t)(b * TSEQ + i)) * CEMB + head * HD;
#pragma unroll
            for (int nd = 0; nd < 8; nd++) {
                int col = nd * 8 + (lane & 3) * 2;
                float2 o1 = *(float2*)(pb + (row * 64 + col) * 4);
                float y0 = (oacc[nd][h * 2 + 0] * f0 + o1.x * f1) * inv;
                float y1 = (oacc[nd][h * 2 + 1] * f0 + o1.y * f1) * inv;
                *(uint32_t*)&g_y16[row_off + col] = packh(y0, y1);
            }
        }
    }
}

// ---------------- launch -------------------------------------------------------
extern "C" void kernel_launch(void* const* d_in, const int* in_sizes, int n_in,
                              void* d_out, int out_size)
{
    const float* x      = (const float*)d_in[0];
    const float* w_qkv  = (const float*)d_in[1];
    const float* b_qkv  = (const float*)d_in[2];
    const float* w_proj = (const float*)d_in[3];
    const float* b_proj = (const float*)d_in[4];
    float* out = (float*)d_out;

    cudaFuncSetAttribute(gemm_mma<0>,
                         cudaFuncAttributeMaxDynamicSharedMemorySize, GSMEM);
    cudaFuncSetAttribute(gemm_mma<1>,
                         cudaFuncAttributeMaxDynamicSharedMemorySize, GSMEM);
    cudaFuncSetAttribute(attn_mma,
                         cudaFuncAttributeMaxDynamicSharedMemorySize, ATTN_SM);

    int n_x = MROWS * CEMB;
    conv_f16_x<<<n_x / 4 / 256, 256>>>(x, n_x);
    conv_f16_T<0><<<dim3(3 * CEMB / 32, CEMB / 32), 256>>>(w_qkv, CEMB, 3 * CEMB);
    conv_f16_T<1><<<dim3(CEMB / 32, CEMB / 32), 256>>>(w_proj, CEMB, CEMB);

    gemm_mma<0><<<dim3(3 * CEMB / 128, MROWS / 128), 256, GSMEM>>>(b_qkv, nullptr);
    attn_mma<<<dim3(TSEQ / 128, BATCH * NH), 512, ATTN_SM>>>();
    gemm_mma<1><<<dim3(CEMB / 128, MROWS / 128), 256, GSMEM>>>(b_proj, out);
}

// round 12
// speedup vs baseline: 2.4940x; 1.0164x over previous
#include <cuda_runtime.h>
#include <cuda_fp16.h>
#include <cstdint>
#include <math.h>

#define BATCH 2
#define TSEQ  4096
#define NH    16
#define HD    64
#define CEMB  1024
#define MROWS (BATCH*TSEQ)          // 8192
#define SCALE2 0.1803368801111204f  // (1/8) * log2(e)

// ---------------- scratch (fp16 operands) --------------------------------------
__device__ __half g_x16[(size_t)MROWS*CEMB];
__device__ __half g_y16[(size_t)MROWS*CEMB];
__device__ __half g_wq16[(size_t)3*CEMB*CEMB];   // [N,K] K-major
__device__ __half g_wp16[(size_t)CEMB*CEMB];
__device__ __half g_q16[(size_t)BATCH*NH*TSEQ*HD];
__device__ __half g_k16[(size_t)BATCH*NH*TSEQ*HD];
__device__ __half g_v16[(size_t)BATCH*NH*TSEQ*HD];

// ---------------- PTX helpers --------------------------------------------------
__device__ __forceinline__ uint32_t smem_u32(const void* p) {
    uint32_t a;
    asm("{ .reg .u64 t; cvta.to.shared.u64 t, %1; cvt.u32.u64 %0, t; }"
        : "=r"(a) : "l"(p));
    return a;
}
__device__ __forceinline__ void cpasync16(uint32_t saddr, const void* g) {
    asm volatile("cp.async.cg.shared.global [%0], [%1], 16;"
                 :: "r"(saddr), "l"(g) : "memory");
}
#define CP_COMMIT() asm volatile("cp.async.commit_group;" ::: "memory")
#define CP_WAIT2()  asm volatile("cp.async.wait_group 2;" ::: "memory")
#define CP_WAIT1()  asm volatile("cp.async.wait_group 1;" ::: "memory")
#define CP_WAIT0()  asm volatile("cp.async.wait_group 0;" ::: "memory")

__device__ __forceinline__ void ldmx4(uint32_t* r, uint32_t addr) {
    asm volatile("ldmatrix.sync.aligned.m8n8.x4.shared.b16 {%0,%1,%2,%3}, [%4];"
        : "=r"(r[0]), "=r"(r[1]), "=r"(r[2]), "=r"(r[3]) : "r"(addr));
}
__device__ __forceinline__ void ldmx2(uint32_t* r, uint32_t addr) {
    asm volatile("ldmatrix.sync.aligned.m8n8.x2.shared.b16 {%0,%1}, [%2];"
        : "=r"(r[0]), "=r"(r[1]) : "r"(addr));
}
__device__ __forceinline__ void ldmx4t(uint32_t* r, uint32_t addr) {
    asm volatile("ldmatrix.sync.aligned.m8n8.x4.trans.shared.b16 {%0,%1,%2,%3}, [%4];"
        : "=r"(r[0]), "=r"(r[1]), "=r"(r[2]), "=r"(r[3]) : "r"(addr));
}
__device__ __forceinline__ void mma16816(float* d, const uint32_t* a,
                                         const uint32_t* b) {
    asm volatile(
        "mma.sync.aligned.m16n8k16.row.col.f32.f16.f16.f32 "
        "{%0,%1,%2,%3}, {%4,%5,%6,%7}, {%8,%9}, {%0,%1,%2,%3};"
        : "+f"(d[0]), "+f"(d[1]), "+f"(d[2]), "+f"(d[3])
        : "r"(a[0]), "r"(a[1]), "r"(a[2]), "r"(a[3]), "r"(b[0]), "r"(b[1]));
}

__device__ __forceinline__ float ex2(float x) {
    float r;
    asm("ex2.approx.ftz.f32 %0, %1;" : "=f"(r) : "f"(x));
    return r;
}
__device__ __forceinline__ uint32_t ex2h2(uint32_t x) {
    uint32_t r;
    asm("ex2.approx.f16x2 %0, %1;" : "=r"(r) : "r"(x));
    return r;
}
__device__ __forceinline__ float2 h2f2(uint32_t u) {
    __half2 h = *(__half2*)&u;
    return __half22float2(h);
}
__device__ __forceinline__ uint32_t packh(float x, float y) {
    __half2 t = __floats2half2_rn(x, y);
    return *(uint32_t*)&t;
}

// ---------------- conversion kernels -------------------------------------------
__global__ void conv_f16_x(const float* __restrict__ src, int n) {
    int i = (blockIdx.x * 256 + threadIdx.x) * 4;
    if (i < n) {
        float4 v = *(const float4*)&src[i];
        uint2 p;
        p.x = packh(v.x, v.y);
        p.y = packh(v.z, v.w);
        *(uint2*)&g_x16[i] = p;
    }
}
template <int W>
__global__ void conv_f16_T(const float* __restrict__ w, int K, int N) {
    __shared__ float t[32][33];
    __half* dT = (W == 0) ? g_wq16 : g_wp16;
    int n0 = blockIdx.x * 32, k0 = blockIdx.y * 32;
    int tx = threadIdx.x & 31, ty = threadIdx.x >> 5;
    for (int r = ty; r < 32; r += 8)
        t[r][tx] = w[(size_t)(k0 + r) * N + n0 + tx];
    __syncthreads();
    for (int r = ty; r < 32; r += 8)
        dT[(size_t)(n0 + r) * K + k0 + tx] = __float2half_rn(t[tx][r]);
}

// ---------------- fp16 GEMM, 3-stage cp.async, 2 CTAs/SM -----------------------
#define BK    64
#define ROWB  144
#define MATB  (128*ROWB)            // 18432
#define STAGEB (2*MATB)             // 36864
#define GSMEM (3*STAGEB)            // 110592

template <int MODE>
__global__ __launch_bounds__(256, 2)
void gemm_mma(const float* __restrict__ bias, float* __restrict__ out)
{
    extern __shared__ __align__(16) char sm[];
    uint32_t smb = smem_u32(sm);

    const __half* A16 = (MODE == 0) ? g_x16 : g_y16;
    const __half* B16 = (MODE == 0) ? g_wq16 : g_wp16;

    int tid = threadIdx.x;
    int wid = tid >> 5, lane = tid & 31;
    int wm = wid >> 2, wn = wid & 3;
    int mBase = blockIdx.y * 128, nBase = blockIdx.x * 128;

    float acc[4][4][4];
#pragma unroll
    for (int mi = 0; mi < 4; mi++)
#pragma unroll
        for (int ni = 0; ni < 4; ni++)
#pragma unroll
            for (int q = 0; q < 4; q++) acc[mi][ni][q] = 0.f;

    auto load_stage = [&](int st, int kt) {
        int k0 = kt * BK;
        uint32_t sb = smb + st * STAGEB;
#pragma unroll
        for (int c = tid; c < 1024; c += 256) {
            int row = c >> 3, ch = c & 7;
            cpasync16(sb + row * ROWB + ch * 16,
                      A16 + (size_t)(mBase + row) * CEMB + k0 + ch * 8);
        }
#pragma unroll
        for (int c = tid; c < 1024; c += 256) {
            int row = c >> 3, ch = c & 7;
            cpasync16(sb + MATB + row * ROWB + ch * 16,
                      B16 + (size_t)(nBase + row) * CEMB + k0 + ch * 8);
        }
    };

    int g = lane >> 3, w = lane & 7;
    uint32_t a_row = (wm * 64 + ((g & 1) << 3) + w) * ROWB;
    uint32_t b_row = (wn * 32 + w) * ROWB;
    uint32_t ka_off = ((g >> 1) << 3) * 2;
    uint32_t kb_off = ((g & 1) << 3) * 2;

    load_stage(0, 0); CP_COMMIT();
    load_stage(1, 1); CP_COMMIT();

    for (int kt = 0; kt < 16; kt++) {
        if (kt < 15) CP_WAIT1(); else CP_WAIT0();
        __syncthreads();
        if (kt + 2 < 16) { load_stage((kt + 2) % 3, kt + 2); CP_COMMIT(); }

        uint32_t bA = smb + (kt % 3) * STAGEB;
        uint32_t bB = bA + MATB;

#pragma unroll
        for (int ks = 0; ks < 4; ks++) {
            uint32_t ka = ks * 32 + ka_off;
            uint32_t kb = ks * 32 + kb_off;
            uint32_t ah[4][4], bh[4][2];
#pragma unroll
            for (int mi = 0; mi < 4; mi++)
                ldmx4(ah[mi], bA + a_row + mi * 16 * ROWB + ka);
#pragma unroll
            for (int ni = 0; ni < 4; ni++)
                ldmx2(bh[ni], bB + b_row + ni * 8 * ROWB + kb);
#pragma unroll
            for (int mi = 0; mi < 4; mi++)
#pragma unroll
                for (int ni = 0; ni < 4; ni++)
                    mma16816(acc[mi][ni], ah[mi], bh[ni]);
        }
        __syncthreads();
    }

    int r_in = lane >> 2, c_in = (lane & 3) * 2;
#pragma unroll
    for (int mi = 0; mi < 4; mi++) {
#pragma unroll
        for (int half = 0; half < 2; half++) {
            int m = mBase + wm * 64 + mi * 16 + r_in + half * 8;
#pragma unroll
            for (int ni = 0; ni < 4; ni++) {
                int n = nBase + wn * 32 + ni * 8 + c_in;
                float v0 = acc[mi][ni][half * 2 + 0] + bias[n];
                float v1 = acc[mi][ni][half * 2 + 1] + bias[n + 1];
                if (MODE == 0) {
                    int b = m >> 12, t = m & 4095;
                    int sect = n >> 10, cc = n & 1023;
                    int head = cc >> 6, d0 = cc & 63;
                    size_t off = (((size_t)(b * NH + head)) * TSEQ + t) * HD + d0;
                    __half* dst = (sect == 0) ? g_q16 : (sect == 1) ? g_k16 : g_v16;
                    *(uint32_t*)&dst[off] = packh(v0, v1);
                } else {
                    *(float2*)&out[(size_t)m * CEMB + n] = make_float2(v0, v1);
                }
            }
        }
    }
}

// ---------------- fp16 HMMA block-sparse flash attention -----------------------
// 64 q-rows per CTA, 256 threads (8 warps: 4 row-groups x 2 col-halves),
// 2 CTAs/SM. Two dense KV buffers + small global buffer; strided slabs and
// merge slabs overlay the dense buffers after barriers.
#define SMQ    0                            // 64 rows x 144 = 9216
#define SB0    9216
#define SB1    46080
#define SBG    82944                        // K16 (2304) + V16 (2304) -> 87552
#define SLAB   9216                         // strided slabs overlay
#define SLABW  12288                        // 3 stages x 4096
#define SMRG   9216                         // merge slabs overlay
#define MERGE_B 4352
#define ATTN_SM (SLAB + 8*SLABW)            // 107520

// MODE: 0 = fully valid, 1 = upper (c>r), 2 = lower (c<=r), 3 = general
template <int NNI, int MODE>
__device__ __forceinline__ void dense_block(
    uint32_t smb, uint32_t kst, uint32_t vst, int lane, int lr0, int rblk,
    int colbase, int i0, int jb, float (&oacc)[8][4], float (&m)[2], float (&l)[2])
{
    const int NKK = NNI / 2;
    int g = lane >> 3, w = lane & 7;
    uint32_t arow = smb + SMQ + (lr0 + ((g & 1) << 3) + w) * 144;
    uint32_t ka = (g >> 1) * 16;
    uint32_t kboff = (g & 1) * 16;

    unsigned skipmask = 0;
    if (MODE == 1) {
#pragma unroll
        for (int ni = 0; ni < NNI; ni++)
            if (colbase + ni * 8 + 7 < rblk) skipmask |= 1u << ni;
    } else if (MODE == 2) {
#pragma unroll
        for (int ni = 0; ni < NNI; ni++)
            if (colbase + ni * 8 > rblk + 15) skipmask |= 1u << ni;
    }

    float sacc[NNI][4];
#pragma unroll
    for (int ni = 0; ni < NNI; ni++)
#pragma unroll
        for (int q = 0; q < 4; q++) sacc[ni][q] = 0.f;

#pragma unroll
    for (int ks = 0; ks < 4; ks++) {
        uint32_t q4[4];
        ldmx4(q4, arow + ks * 32 + ka);
#pragma unroll
        for (int ni = 0; ni < NNI; ni++) {
            if ((skipmask >> ni) & 1) continue;
            uint32_t kb2[2];
            ldmx2(kb2, kst + (colbase + ni * 8 + w) * 144 + kboff + ks * 32);
            mma16816(sacc[ni], q4, kb2);
        }
    }

    int c0 = (lane & 3) * 2;
    float mb0 = -1e30f, mb1 = -1e30f;
#pragma unroll
    for (int ni = 0; ni < NNI; ni++) {
        if ((skipmask >> ni) & 1) continue;
        int jB = jb + ni * 8 + c0;
#pragma unroll
        for (int q = 0; q < 4; q++) {
            int jj = jB + (q & 1);
            int ii = (q < 2) ? i0 : i0 + 8;
            bool ok;
            if (MODE == 0) ok = true;
            else if (MODE == 1) ok = (ii - jj) <= 256;
            else if (MODE == 2) ok = jj <= ii;
            else {
                int diff = ii - jj;
                ok = diff >= 0 && (diff < 256 || (diff & 127) == 0 || jj < 16);
            }
            sacc[ni][q] = ok ? sacc[ni][q] * SCALE2 : -1e30f;
        }
        mb0 = fmaxf(mb0, fmaxf(sacc[ni][0], sacc[ni][1]));
        mb1 = fmaxf(mb1, fmaxf(sacc[ni][2], sacc[ni][3]));
    }
    mb0 = fmaxf(mb0, __shfl_xor_sync(0xffffffffu, mb0, 1));
    mb0 = fmaxf(mb0, __shfl_xor_sync(0xffffffffu, mb0, 2));
    mb1 = fmaxf(mb1, __shfl_xor_sync(0xffffffffu, mb1, 1));
    mb1 = fmaxf(mb1, __shfl_xor_sync(0xffffffffu, mb1, 2));

    float mn0 = fmaxf(fmaxf(m[0], mb0), -1e28f);
    float mn1 = fmaxf(fmaxf(m[1], mb1), -1e28f);
    float cs0 = ex2(m[0] - mn0), cs1 = ex2(m[1] - mn1);

    uint32_t pp[NNI][2];
    float ls0 = 0.f, ls1 = 0.f;
#pragma unroll
    for (int ni = 0; ni < NNI; ni++) {
        if ((skipmask >> ni) & 1) { pp[ni][0] = 0u; pp[ni][1] = 0u; continue; }
        uint32_t a0 = packh(sacc[ni][0] - mn0, sacc[ni][1] - mn0);
        uint32_t a1 = packh(sacc[ni][2] - mn1, sacc[ni][3] - mn1);
        uint32_t p0 = ex2h2(a0), p1 = ex2h2(a1);
        pp[ni][0] = p0; pp[ni][1] = p1;
        float2 f0 = h2f2(p0), f1 = h2f2(p1);
        ls0 += f0.x + f0.y; ls1 += f1.x + f1.y;
    }
    ls0 += __shfl_xor_sync(0xffffffffu, ls0, 1);
    ls0 += __shfl_xor_sync(0xffffffffu, ls0, 2);
    ls1 += __shfl_xor_sync(0xffffffffu, ls1, 1);
    ls1 += __shfl_xor_sync(0xffffffffu, ls1, 2);
    l[0] = l[0] * cs0 + ls0; m[0] = mn0;
    l[1] = l[1] * cs1 + ls1; m[1] = mn1;
#pragma unroll
    for (int nd = 0; nd < 8; nd++) {
        oacc[nd][0] *= cs0; oacc[nd][1] *= cs0;
        oacc[nd][2] *= cs1; oacc[nd][3] *= cs1;
    }

    int jrow = ((g & 1) << 3) + w;
    int dcol = (g >> 1) * 16;
#pragma unroll
    for (int kk = 0; kk < NKK; kk++) {
        if (((skipmask >> (2 * kk)) & 3u) == 3u) continue;
        uint32_t pa[4] = { pp[2*kk][0], pp[2*kk][1], pp[2*kk+1][0], pp[2*kk+1][1] };
#pragma unroll
        for (int gv = 0; gv < 2; gv++) {
            uint32_t vh4[2][4];
#pragma unroll
            for (int u = 0; u < 2; u++) {
                int nd2 = gv * 2 + u;
                ldmx4t(vh4[u], vst + (colbase + kk * 16 + jrow) * 144 + nd2 * 32 + dcol);
            }
#pragma unroll
            for (int u = 0; u < 2; u++) {
                int nd2 = gv * 2 + u;
                mma16816(oacc[nd2 * 2],     pa, vh4[u]);
                mma16816(oacc[nd2 * 2 + 1], pa, vh4[u] + 2);
            }
        }
    }
}

__global__ __launch_bounds__(256, 2)
void attn_mma()
{
    extern __shared__ __align__(16) char sm[];
    uint32_t smb = smem_u32(sm);
    int tid = threadIdx.x, lane = tid & 31, wid = tid >> 5;
    int rg = wid >> 1, ch2 = wid & 1;        // 4 row-groups x 2 col-halves
    int qt = (gridDim.x - 1) - blockIdx.x;   // heavy-first; 64-row tiles
    int qb = qt >> 1, s = qt & 1;            // 128-block id, sub-half
    int bh = blockIdx.y;

    auto stage_rows = [&](uint32_t dst, const __half* src, int nrows) {
        for (int c = tid; c < nrows * 8; c += 256) {
            int row = c >> 3, ch = c & 7;
            cpasync16(dst + row * 144 + ch * 16, src + (size_t)row * HD + ch * 8);
        }
    };
    size_t hb = (size_t)bh * TSEQ * HD;

    // stage Q (64 rows)
    stage_rows(smb + SMQ, g_q16 + hb + (size_t)qt * 64 * HD, 64);

    float oacc[8][4];
#pragma unroll
    for (int nd = 0; nd < 8; nd++)
#pragma unroll
        for (int q = 0; q < 4; q++) oacc[nd][q] = 0.f;
    float m[2] = { -1e30f, -1e30f }, l[2] = { 0.f, 0.f };
    int lr0 = rg * 16;                        // local row base (0..48)
    int rblk = s * 64 + lr0;                  // row base within 128-key-block
    int i0 = qt * 64 + lr0 + (lane >> 2);     // global query row

    if (qb >= 3) {
        stage_rows(smb + SB0,         g_k16 + hb + (size_t)(qb - 1) * 128 * HD, 128);
        stage_rows(smb + SB0 + 18432, g_v16 + hb + (size_t)(qb - 1) * 128 * HD, 128);
        CP_COMMIT();
        stage_rows(smb + SB1,         g_k16 + hb + (size_t)(qb - 2) * 128 * HD, 128);
        stage_rows(smb + SB1 + 18432, g_v16 + hb + (size_t)(qb - 2) * 128 * HD, 128);
        CP_COMMIT();
        stage_rows(smb + SBG,        g_k16 + hb, 16);
        stage_rows(smb + SBG + 2304, g_v16 + hb, 16);
        CP_COMMIT();

        CP_WAIT2(); __syncthreads();
        dense_block<8, 0>(smb, smb + SB0, smb + SB0 + 18432, lane, lr0, rblk,
                          ch2 * 64, i0, (qb - 1) * 128 + ch2 * 64, oacc, m, l);
        __syncthreads();                      // done reading SB0
        stage_rows(smb + SB0,         g_k16 + hb + (size_t)qb * 128 * HD, 128);
        stage_rows(smb + SB0 + 18432, g_v16 + hb + (size_t)qb * 128 * HD, 128);
        CP_COMMIT();
        CP_WAIT2();                           // SB1 (qb-2) done
        dense_block<8, 1>(smb, smb + SB1, smb + SB1 + 18432, lane, lr0, rblk,
                          ch2 * 64, i0, (qb - 2) * 128 + ch2 * 64, oacc, m, l);
        CP_WAIT0(); __syncthreads();
        dense_block<8, 2>(smb, smb + SB0, smb + SB0 + 18432, lane, lr0, rblk,
                          ch2 * 64, i0, qb * 128 + ch2 * 64, oacc, m, l);
        if (ch2 == 0)
            dense_block<2, 0>(smb, smb + SBG, smb + SBG + 2304, lane, lr0, rblk,
                              0, i0, 0, oacc, m, l);
    } else {
        stage_rows(smb + SB0,         g_k16 + hb, 128);
        stage_rows(smb + SB0 + 18432, g_v16 + hb, 128);
        CP_COMMIT();
        if (qb >= 1) {
            stage_rows(smb + SB1,         g_k16 + hb + (size_t)128 * HD, 128);
            stage_rows(smb + SB1 + 18432, g_v16 + hb + (size_t)128 * HD, 128);
        }
        CP_COMMIT();
        CP_WAIT1(); __syncthreads();
        dense_block<8, 3>(smb, smb + SB0, smb + SB0 + 18432, lane, lr0, rblk,
                          ch2 * 64, i0, ch2 * 64, oacc, m, l);
        if (qb >= 1) {
            if (qb >= 2) {
                __syncthreads();              // done reading SB0
                stage_rows(smb + SB0,         g_k16 + hb + (size_t)256 * HD, 128);
                stage_rows(smb + SB0 + 18432, g_v16 + hb + (size_t)256 * HD, 128);
                CP_COMMIT();
                CP_WAIT1();
            } else {
                CP_WAIT0();
            }
            dense_block<8, 3>(smb, smb + SB1, smb + SB1 + 18432, lane, lr0, rblk,
                              ch2 * 64, i0, 128 + ch2 * 64, oacc, m, l);
            if (qb >= 2) {
                CP_WAIT0(); __syncthreads();
                dense_block<8, 3>(smb, smb + SB0, smb + SB0 + 18432, lane, lr0, rblk,
                                  ch2 * 64, i0, 256 + ch2 * 64, oacc, m, l);
            }
        }
    }

    // ---------- strided diagonals: single-pass, per-warp cp.async pipeline -----
    int nkb = qb - 2;
    if (nkb > 0) {
        __syncthreads();                       // dense buffers dead; slabs overlay
        uint32_t slab = smb + SLAB + wid * SLABW;
        int part = lane & 3, qr = lane >> 2;

        auto stage_kb = [&](int slot, int kb) {
            size_t rowbase = (size_t)kb * 128 + s * 64 + rg * 16;
            const __half* Ksrc = g_k16 + hb + rowbase * HD;
            const __half* Vsrc = g_v16 + hb + rowbase * HD;
            uint32_t base = slab + slot * 4096;
#pragma unroll
            for (int c = lane; c < 128; c += 32) {
                int row = c >> 3, ch = c & 7;
                cpasync16(base + row * 128 + ch * 16,
                          Ksrc + (size_t)row * HD + ch * 8);
                cpasync16(base + 2048 + row * 128 + ch * 16,
                          Vsrc + (size_t)row * HD + ch * 8);
            }
            CP_COMMIT();
        };

        int nexts = ch2;
#pragma unroll
        for (int st2 = 0; st2 < 3; st2++) {
            if (nexts < nkb) { stage_kb(st2, nexts); nexts += 2; }
        }

        int it = 0;
        for (int kb = ch2; kb < nkb; kb += 2, it++) {
            int ahead = (nexts - kb) >> 1;
            if (ahead >= 3) CP_WAIT2();
            else if (ahead == 2) CP_WAIT1();
            else CP_WAIT0();
            __syncwarp();

            uint32_t st = slab + (it % 3) * 4096;
#pragma unroll
            for (int h = 0; h < 2; h++) {
                int lr = qr + h * 8;
                int rowin128 = s * 64 + rg * 16 + lr;
                float sc;
                if (kb == 0 && rowin128 < 16) {
                    sc = -1e30f;
                } else {
                    uint32_t kaddr = st + lr * 128 + part * 32;
                    uint32_t qaddr = smb + SMQ + (rg * 16 + lr) * 144 + part * 32;
                    float sum = 0.f;
#pragma unroll
                    for (int seg = 0; seg < 2; seg++) {
                        uint32_t k4[4], q4[4];
                        asm volatile("ld.shared.v4.b32 {%0,%1,%2,%3}, [%4];"
                            : "=r"(k4[0]), "=r"(k4[1]), "=r"(k4[2]), "=r"(k4[3])
                            : "r"(kaddr + seg * 16));
                        asm volatile("ld.shared.v4.b32 {%0,%1,%2,%3}, [%4];"
                            : "=r"(q4[0]), "=r"(q4[1]), "=r"(q4[2]), "=r"(q4[3])
                            : "r"(qaddr + seg * 16));
#pragma unroll
                        for (int u = 0; u < 4; u++) {
                            float2 qf = h2f2(q4[u]), kf = h2f2(k4[u]);
                            sum += qf.x * kf.x + qf.y * kf.y;
                        }
                    }
                    sum += __shfl_xor_sync(0xffffffffu, sum, 1);
                    sum += __shfl_xor_sync(0xffffffffu, sum, 2);
                    sc = sum * SCALE2;
                }
                float mold = m[h];
                float mx = fmaxf(fmaxf(mold, sc), -1e28f);
                float p = ex2(sc - mx);
                if (__any_sync(0xffffffffu, mx > mold)) {
                    float cs = ex2(mold - mx);
                    l[h] = l[h] * cs + p;
                    m[h] = mx;
#pragma unroll
                    for (int nd = 0; nd < 8; nd++) {
                        oacc[nd][h * 2 + 0] *= cs;
                        oacc[nd][h * 2 + 1] *= cs;
                    }
                } else {
                    l[h] += p;
                }
                uint32_t vaddr = st + 2048 + lr * 128 + part * 4;
#pragma unroll
                for (int nd = 0; nd < 8; nd++) {
                    uint32_t vv;
                    asm volatile("ld.shared.b32 %0, [%1];"
                        : "=r"(vv) : "r"(vaddr + nd * 16));
                    float2 vf = h2f2(vv);
                    oacc[nd][h * 2 + 0] += p * vf.x;
                    oacc[nd][h * 2 + 1] += p * vf.y;
                }
            }

            if (nexts < nkb) {
                __syncwarp();
                stage_kb(it % 3, nexts);
                nexts += 2;
            }
        }
    }

    // pairwise split-softmax merge, then epilogue
    __syncthreads();
    {
        char* mb = sm + SMRG + wid * MERGE_B;
#pragma unroll
        for (int h = 0; h < 2; h++) {
            int row = (lane >> 2) + h * 8;
#pragma unroll
            for (int nd = 0; nd < 8; nd++) {
                int col = nd * 8 + (lane & 3) * 2;
                *(float2*)(mb + (row * 64 + col) * 4) =
                    make_float2(oacc[nd][h * 2], oacc[nd][h * 2 + 1]);
            }
            if ((lane & 3) == 0)
                *(float2*)(mb + 4096 + row * 8) = make_float2(m[h], l[h]);
        }
    }
    __syncthreads();
    if (ch2 == 0) {
        char* pb = sm + SMRG + (wid + 1) * MERGE_B;
        int b = bh >> 4, head = bh & 15;
#pragma unroll
        for (int h = 0; h < 2; h++) {
            int row = (lane >> 2) + h * 8;
            float2 ml = *(float2*)(pb + 4096 + row * 8);
            float mx = fmaxf(m[h], ml.x);
            float f0 = ex2(m[h] - mx), f1 = ex2(ml.x - mx);
            float L = l[h] * f0 + ml.y * f1;
            float inv = 1.f / L;
            int i = qt * 64 + rg * 16 + row;
            size_t row_off = ((size_t)(b * TSEQ + i)) * CEMB + head * HD;
#pragma unroll
            for (int nd = 0; nd < 8; nd++) {
                int col = nd * 8 + (lane & 3) * 2;
                float2 o1 = *(float2*)(pb + (row * 64 + col) * 4);
                float y0 = (oacc[nd][h * 2 + 0] * f0 + o1.x * f1) * inv;
                float y1 = (oacc[nd][h * 2 + 1] * f0 + o1.y * f1) * inv;
                *(uint32_t*)&g_y16[row_off + col] = packh(y0, y1);
            }
        }
    }
}

// ---------------- launch -------------------------------------------------------
extern "C" void kernel_launch(void* const* d_in, const int* in_sizes, int n_in,
                              void* d_out, int out_size)
{
    const float* x      = (const float*)d_in[0];
    const float* w_qkv  = (const float*)d_in[1];
    const float* b_qkv  = (const float*)d_in[2];
    const float* w_proj = (const float*)d_in[3];
    const float* b_proj = (const float*)d_in[4];
    float* out = (float*)d_out;

    cudaFuncSetAttribute(gemm_mma<0>,
                         cudaFuncAttributeMaxDynamicSharedMemorySize, GSMEM);
    cudaFuncSetAttribute(gemm_mma<1>,
                         cudaFuncAttributeMaxDynamicSharedMemorySize, GSMEM);
    cudaFuncSetAttribute(attn_mma,
                         cudaFuncAttributeMaxDynamicSharedMemorySize, ATTN_SM);

    int n_x = MROWS * CEMB;
    conv_f16_x<<<n_x / 4 / 256, 256>>>(x, n_x);
    conv_f16_T<0><<<dim3(3 * CEMB / 32, CEMB / 32), 256>>>(w_qkv, CEMB, 3 * CEMB);
    conv_f16_T<1><<<dim3(CEMB / 32, CEMB / 32), 256>>>(w_proj, CEMB, CEMB);

    gemm_mma<0><<<dim3(3 * CEMB / 128, MROWS / 128), 256, GSMEM>>>(b_qkv, nullptr);
    attn_mma<<<dim3(TSEQ / 64, BATCH * NH), 256, ATTN_SM>>>();
    gemm_mma<1><<<dim3(CEMB / 128, MROWS / 128), 256, GSMEM>>>(b_proj, out);
}

// round 13
// speedup vs baseline: 2.5671x; 1.0293x over previous
#include <cuda_runtime.h>
#include <cuda_fp16.h>
#include <cstdint>
#include <math.h>

#define BATCH 2
#define TSEQ  4096
#define NH    16
#define HD    64
#define CEMB  1024
#define MROWS (BATCH*TSEQ)          // 8192
#define SCALE2 0.1803368801111204f  // (1/8) * log2(e)

// ---------------- scratch (fp16 operands) --------------------------------------
__device__ __half g_x16[(size_t)MROWS*CEMB];
__device__ __half g_y16[(size_t)MROWS*CEMB];
__device__ __half g_wq16[(size_t)3*CEMB*CEMB];   // [N,K] K-major
__device__ __half g_wp16[(size_t)CEMB*CEMB];
__device__ __half g_q16[(size_t)BATCH*NH*TSEQ*HD];
__device__ __half g_k16[(size_t)BATCH*NH*TSEQ*HD];
__device__ __half g_v16[(size_t)BATCH*NH*TSEQ*HD];

// ---------------- PTX helpers --------------------------------------------------
__device__ __forceinline__ uint32_t smem_u32(const void* p) {
    uint32_t a;
    asm("{ .reg .u64 t; cvta.to.shared.u64 t, %1; cvt.u32.u64 %0, t; }"
        : "=r"(a) : "l"(p));
    return a;
}
__device__ __forceinline__ void cpasync16(uint32_t saddr, const void* g) {
    asm volatile("cp.async.cg.shared.global [%0], [%1], 16;"
                 :: "r"(saddr), "l"(g) : "memory");
}
#define CP_COMMIT() asm volatile("cp.async.commit_group;" ::: "memory")
#define CP_WAIT2()  asm volatile("cp.async.wait_group 2;" ::: "memory")
#define CP_WAIT1()  asm volatile("cp.async.wait_group 1;" ::: "memory")
#define CP_WAIT0()  asm volatile("cp.async.wait_group 0;" ::: "memory")

__device__ __forceinline__ void ldmx4(uint32_t* r, uint32_t addr) {
    asm volatile("ldmatrix.sync.aligned.m8n8.x4.shared.b16 {%0,%1,%2,%3}, [%4];"
        : "=r"(r[0]), "=r"(r[1]), "=r"(r[2]), "=r"(r[3]) : "r"(addr));
}
__device__ __forceinline__ void ldmx2(uint32_t* r, uint32_t addr) {
    asm volatile("ldmatrix.sync.aligned.m8n8.x2.shared.b16 {%0,%1}, [%2];"
        : "=r"(r[0]), "=r"(r[1]) : "r"(addr));
}
__device__ __forceinline__ void ldmx4t(uint32_t* r, uint32_t addr) {
    asm volatile("ldmatrix.sync.aligned.m8n8.x4.trans.shared.b16 {%0,%1,%2,%3}, [%4];"
        : "=r"(r[0]), "=r"(r[1]), "=r"(r[2]), "=r"(r[3]) : "r"(addr));
}
__device__ __forceinline__ void mma16816(float* d, const uint32_t* a,
                                         const uint32_t* b) {
    asm volatile(
        "mma.sync.aligned.m16n8k16.row.col.f32.f16.f16.f32 "
        "{%0,%1,%2,%3}, {%4,%5,%6,%7}, {%8,%9}, {%0,%1,%2,%3};"
        : "+f"(d[0]), "+f"(d[1]), "+f"(d[2]), "+f"(d[3])
        : "r"(a[0]), "r"(a[1]), "r"(a[2]), "r"(a[3]), "r"(b[0]), "r"(b[1]));
}

__device__ __forceinline__ float ex2(float x) {
    float r;
    asm("ex2.approx.ftz.f32 %0, %1;" : "=f"(r) : "f"(x));
    return r;
}
__device__ __forceinline__ uint32_t ex2h2(uint32_t x) {
    uint32_t r;
    asm("ex2.approx.f16x2 %0, %1;" : "=r"(r) : "r"(x));
    return r;
}
__device__ __forceinline__ float2 h2f2(uint32_t u) {
    __half2 h = *(__half2*)&u;
    return __half22float2(h);
}
__device__ __forceinline__ uint32_t packh(float x, float y) {
    __half2 t = __floats2half2_rn(x, y);
    return *(uint32_t*)&t;
}

// ---------------- merged conversion kernel --------------------------------------
// blocks [0, 8192): x fp32 -> fp16
// blocks [8192, 11264): w_qkv transpose+convert (96 x 32 tiles)
// blocks [11264, 12288): w_proj transpose+convert (32 x 32 tiles)
__global__ void conv_all(const float* __restrict__ x,
                         const float* __restrict__ wq,
                         const float* __restrict__ wp)
{
    __shared__ float t[32][33];
    int bid = blockIdx.x;
    if (bid < 8192) {
        int i = (bid * 256 + threadIdx.x) * 4;
        float4 v = *(const float4*)&x[i];
        uint2 p;
        p.x = packh(v.x, v.y);
        p.y = packh(v.z, v.w);
        *(uint2*)&g_x16[i] = p;
        return;
    }
    const float* w;
    __half* dT;
    int n0, k0, N;
    if (bid < 11264) {
        int idx = bid - 8192;
        w = wq; dT = g_wq16; N = 3 * CEMB;
        n0 = (idx % 96) * 32; k0 = (idx / 96) * 32;
    } else {
        int idx = bid - 11264;
        w = wp; dT = g_wp16; N = CEMB;
        n0 = (idx & 31) * 32; k0 = (idx >> 5) * 32;
    }
    int tx = threadIdx.x & 31, ty = threadIdx.x >> 5;
    for (int r = ty; r < 32; r += 8)
        t[r][tx] = w[(size_t)(k0 + r) * N + n0 + tx];
    __syncthreads();
    for (int r = ty; r < 32; r += 8)
        dT[(size_t)(n0 + r) * CEMB + k0 + tx] = __float2half_rn(t[tx][r]);
}

// ---------------- fp16 GEMM, 3-stage cp.async, 2 CTAs/SM -----------------------
#define BK    64
#define ROWB  144
#define MATB  (128*ROWB)            // 18432
#define STAGEB (2*MATB)             // 36864
#define GSMEM (3*STAGEB)            // 110592

template <int MODE>
__global__ __launch_bounds__(256, 2)
void gemm_mma(const float* __restrict__ bias, float* __restrict__ out)
{
    extern __shared__ __align__(16) char sm[];
    uint32_t smb = smem_u32(sm);

    const __half* A16 = (MODE == 0) ? g_x16 : g_y16;
    const __half* B16 = (MODE == 0) ? g_wq16 : g_wp16;

    int tid = threadIdx.x;
    int wid = tid >> 5, lane = tid & 31;
    int wm = wid >> 2, wn = wid & 3;
    int mBase = blockIdx.y * 128, nBase = blockIdx.x * 128;

    float acc[4][4][4];
#pragma unroll
    for (int mi = 0; mi < 4; mi++)
#pragma unroll
        for (int ni = 0; ni < 4; ni++)
#pragma unroll
            for (int q = 0; q < 4; q++) acc[mi][ni][q] = 0.f;

    auto load_stage = [&](int st, int kt) {
        int k0 = kt * BK;
        uint32_t sb = smb + st * STAGEB;
#pragma unroll
        for (int c = tid; c < 1024; c += 256) {
            int row = c >> 3, ch = c & 7;
            cpasync16(sb + row * ROWB + ch * 16,
                      A16 + (size_t)(mBase + row) * CEMB + k0 + ch * 8);
        }
#pragma unroll
        for (int c = tid; c < 1024; c += 256) {
            int row = c >> 3, ch = c & 7;
            cpasync16(sb + MATB + row * ROWB + ch * 16,
                      B16 + (size_t)(nBase + row) * CEMB + k0 + ch * 8);
        }
    };

    int g = lane >> 3, w = lane & 7;
    uint32_t a_row = (wm * 64 + ((g & 1) << 3) + w) * ROWB;
    uint32_t b_row = (wn * 32 + w) * ROWB;
    uint32_t ka_off = ((g >> 1) << 3) * 2;
    uint32_t kb_off = ((g & 1) << 3) * 2;

    load_stage(0, 0); CP_COMMIT();
    load_stage(1, 1); CP_COMMIT();

    for (int kt = 0; kt < 16; kt++) {
        if (kt < 15) CP_WAIT1(); else CP_WAIT0();
        __syncthreads();
        if (kt + 2 < 16) { load_stage((kt + 2) % 3, kt + 2); CP_COMMIT(); }

        uint32_t bA = smb + (kt % 3) * STAGEB;
        uint32_t bB = bA + MATB;

#pragma unroll
        for (int ks = 0; ks < 4; ks++) {
            uint32_t ka = ks * 32 + ka_off;
            uint32_t kb = ks * 32 + kb_off;
            uint32_t ah[4][4], bh[4][2];
#pragma unroll
            for (int mi = 0; mi < 4; mi++)
                ldmx4(ah[mi], bA + a_row + mi * 16 * ROWB + ka);
#pragma unroll
            for (int ni = 0; ni < 4; ni++)
                ldmx2(bh[ni], bB + b_row + ni * 8 * ROWB + kb);
#pragma unroll
            for (int mi = 0; mi < 4; mi++)
#pragma unroll
                for (int ni = 0; ni < 4; ni++)
                    mma16816(acc[mi][ni], ah[mi], bh[ni]);
        }
        __syncthreads();
    }

    int r_in = lane >> 2, c_in = (lane & 3) * 2;
#pragma unroll
    for (int mi = 0; mi < 4; mi++) {
#pragma unroll
        for (int half = 0; half < 2; half++) {
            int m = mBase + wm * 64 + mi * 16 + r_in + half * 8;
#pragma unroll
            for (int ni = 0; ni < 4; ni++) {
                int n = nBase + wn * 32 + ni * 8 + c_in;
                float v0 = acc[mi][ni][half * 2 + 0] + bias[n];
                float v1 = acc[mi][ni][half * 2 + 1] + bias[n + 1];
                if (MODE == 0) {
                    int b = m >> 12, t = m & 4095;
                    int sect = n >> 10, cc = n & 1023;
                    int head = cc >> 6, d0 = cc & 63;
                    size_t off = (((size_t)(b * NH + head)) * TSEQ + t) * HD + d0;
                    __half* dst = (sect == 0) ? g_q16 : (sect == 1) ? g_k16 : g_v16;
                    *(uint32_t*)&dst[off] = packh(v0, v1);
                } else {
                    *(float2*)&out[(size_t)m * CEMB + n] = make_float2(v0, v1);
                }
            }
        }
    }
}

// ---------------- fp16 HMMA block-sparse flash attention -----------------------
// 64 q-rows per CTA, 256 threads, 2 CTAs/SM. All dense KV staged up front with
// exact (half-tile) footprints; no mid-phase restaging for qb>=3.
#define SMQ    0                            // 9216
#define SBA    9216                         // qb-1 tile: K 18432 + V 18432
#define SLB    46080                        // B+C slab: 55296
#define SBGK   101376                       // global K16 2304 + V16 2304
#define SLAB   9216                         // strided slabs overlay
#define SLABW  12288
#define SMRG   9216                         // merge slabs overlay
#define MERGE_B 4352
#define ATTN_SM (SLAB + 8*SLABW)            // 107520

// MODE: 0 = fully valid, 1 = upper (c>=r within pair), 2 = lower, 3 = general
template <int NNI, int MODE>
__device__ __forceinline__ void dense_block(
    const uint32_t (&qf)[4][4], uint32_t kst, uint32_t vst, int lane, int rblk,
    int colbase, int i0, int jb, float (&oacc)[8][4], float (&m)[2], float (&l)[2])
{
    const int NKK = NNI / 2;
    int g = lane >> 3, w = lane & 7;
    uint32_t kboff = (g & 1) * 16;

    unsigned skipmask = 0;
    if (MODE == 1) {
#pragma unroll
        for (int ni = 0; ni < NNI; ni++)
            if (colbase + ni * 8 + 7 < rblk) skipmask |= 1u << ni;
    } else if (MODE == 2) {
#pragma unroll
        for (int ni = 0; ni < NNI; ni++)
            if (colbase + ni * 8 > rblk + 15) skipmask |= 1u << ni;
    }

    float sacc[NNI][4];
#pragma unroll
    for (int ni = 0; ni < NNI; ni++)
#pragma unroll
        for (int q = 0; q < 4; q++) sacc[ni][q] = 0.f;

#pragma unroll
    for (int ks = 0; ks < 4; ks++) {
#pragma unroll
        for (int ni = 0; ni < NNI; ni++) {
            if ((skipmask >> ni) & 1) continue;
            uint32_t kb2[2];
            ldmx2(kb2, kst + (colbase + ni * 8 + w) * 144 + kboff + ks * 32);
            mma16816(sacc[ni], qf[ks], kb2);
        }
    }

    int c0 = (lane & 3) * 2;
    float mb0 = -1e30f, mb1 = -1e30f;
#pragma unroll
    for (int ni = 0; ni < NNI; ni++) {
        if ((skipmask >> ni) & 1) continue;
        int jB = jb + ni * 8 + c0;
#pragma unroll
        for (int q = 0; q < 4; q++) {
            int jj = jB + (q & 1);
            int ii = (q < 2) ? i0 : i0 + 8;
            bool ok;
            if (MODE == 0) ok = true;
            else if (MODE == 1) ok = (ii - jj) <= 256;
            else if (MODE == 2) ok = jj <= ii;
            else {
                int diff = ii - jj;
                ok = diff >= 0 && (diff < 256 || (diff & 127) == 0 || jj < 16);
            }
            sacc[ni][q] = ok ? sacc[ni][q] * SCALE2 : -1e30f;
        }
        mb0 = fmaxf(mb0, fmaxf(sacc[ni][0], sacc[ni][1]));
        mb1 = fmaxf(mb1, fmaxf(sacc[ni][2], sacc[ni][3]));
    }
    mb0 = fmaxf(mb0, __shfl_xor_sync(0xffffffffu, mb0, 1));
    mb0 = fmaxf(mb0, __shfl_xor_sync(0xffffffffu, mb0, 2));
    mb1 = fmaxf(mb1, __shfl_xor_sync(0xffffffffu, mb1, 1));
    mb1 = fmaxf(mb1, __shfl_xor_sync(0xffffffffu, mb1, 2));

    float mn0 = fmaxf(fmaxf(m[0], mb0), -1e28f);
    float mn1 = fmaxf(fmaxf(m[1], mb1), -1e28f);
    float cs0 = ex2(m[0] - mn0), cs1 = ex2(m[1] - mn1);

    uint32_t pp[NNI][2];
    float ls0 = 0.f, ls1 = 0.f;
#pragma unroll
    for (int ni = 0; ni < NNI; ni++) {
        if ((skipmask >> ni) & 1) { pp[ni][0] = 0u; pp[ni][1] = 0u; continue; }
        uint32_t a0 = packh(sacc[ni][0] - mn0, sacc[ni][1] - mn0);
        uint32_t a1 = packh(sacc[ni][2] - mn1, sacc[ni][3] - mn1);
        uint32_t p0 = ex2h2(a0), p1 = ex2h2(a1);
        pp[ni][0] = p0; pp[ni][1] = p1;
        float2 f0 = h2f2(p0), f1 = h2f2(p1);
        ls0 += f0.x + f0.y; ls1 += f1.x + f1.y;
    }
    ls0 += __shfl_xor_sync(0xffffffffu, ls0, 1);
    ls0 += __shfl_xor_sync(0xffffffffu, ls0, 2);
    ls1 += __shfl_xor_sync(0xffffffffu, ls1, 1);
    ls1 += __shfl_xor_sync(0xffffffffu, ls1, 2);
    l[0] = l[0] * cs0 + ls0; m[0] = mn0;
    l[1] = l[1] * cs1 + ls1; m[1] = mn1;
#pragma unroll
    for (int nd = 0; nd < 8; nd++) {
        oacc[nd][0] *= cs0; oacc[nd][1] *= cs0;
        oacc[nd][2] *= cs1; oacc[nd][3] *= cs1;
    }

    int jrow = ((g & 1) << 3) + w;
    int dcol = (g >> 1) * 16;
#pragma unroll
    for (int kk = 0; kk < NKK; kk++) {
        if (((skipmask >> (2 * kk)) & 3u) == 3u) continue;
        uint32_t pa[4] = { pp[2*kk][0], pp[2*kk][1], pp[2*kk+1][0], pp[2*kk+1][1] };
#pragma unroll
        for (int gv = 0; gv < 2; gv++) {
            uint32_t vh4[2][4];
#pragma unroll
            for (int u = 0; u < 2; u++) {
                int nd2 = gv * 2 + u;
                ldmx4t(vh4[u], vst + (colbase + kk * 16 + jrow) * 144 + nd2 * 32 + dcol);
            }
#pragma unroll
            for (int u = 0; u < 2; u++) {
                int nd2 = gv * 2 + u;
                mma16816(oacc[nd2 * 2],     pa, vh4[u]);
                mma16816(oacc[nd2 * 2 + 1], pa, vh4[u] + 2);
            }
        }
    }
}

__global__ __launch_bounds__(256, 2)
void attn_mma()
{
    extern __shared__ __align__(16) char sm[];
    uint32_t smb = smem_u32(sm);
    int tid = threadIdx.x, lane = tid & 31, wid = tid >> 5;
    int rg = wid >> 1, ch2 = wid & 1;
    int qt = (gridDim.x - 1) - blockIdx.x;   // heavy-first; 64-row tiles
    int qb = qt >> 1, s = qt & 1;
    int bh = blockIdx.y;

    auto stage_rows = [&](uint32_t dst, const __half* src, int nrows) {
        for (int c = tid; c < nrows * 8; c += 256) {
            int row = c >> 3, ch = c & 7;
            cpasync16(dst + row * 144 + ch * 16, src + (size_t)row * HD + ch * 8);
        }
    };
    size_t hb = (size_t)bh * TSEQ * HD;

    stage_rows(smb + SMQ, g_q16 + hb + (size_t)qt * 64 * HD, 64);

    float oacc[8][4];
#pragma unroll
    for (int nd = 0; nd < 8; nd++)
#pragma unroll
        for (int q = 0; q < 4; q++) oacc[nd][q] = 0.f;
    float m[2] = { -1e30f, -1e30f }, l[2] = { 0.f, 0.f };
    int lr0 = rg * 16;
    int rblk = s * 64 + lr0;
    int i0 = qt * 64 + lr0 + (lane >> 2);

    uint32_t qf[4][4];
    int gq = lane >> 3, wq_ = lane & 7;
    uint32_t qrow = smb + SMQ + (lr0 + ((gq & 1) << 3) + wq_) * 144 + (gq >> 1) * 16;

    if (qb >= 3) {
        // group 0: Q + block qb-1 (full)
        stage_rows(smb + SBA,         g_k16 + hb + (size_t)(qb - 1) * 128 * HD, 128);
        stage_rows(smb + SBA + 18432, g_v16 + hb + (size_t)(qb - 1) * 128 * HD, 128);
        CP_COMMIT();
        // group 1: block qb-2 (half for s=1)
        int cminB = s ? 64 : 0, cntB = s ? 64 : 128;
        uint32_t bK = smb + SLB, bV = bK + (uint32_t)cntB * 144;
        stage_rows(bK, g_k16 + hb + ((size_t)(qb - 2) * 128 + cminB) * HD, cntB);
        stage_rows(bV, g_v16 + hb + ((size_t)(qb - 2) * 128 + cminB) * HD, cntB);
        CP_COMMIT();
        // group 2: block qb (half for s=0) + global
        int cntC = s ? 128 : 64;
        uint32_t cK = bV + (uint32_t)cntB * 144, cV = cK + (uint32_t)cntC * 144;
        stage_rows(cK, g_k16 + hb + (size_t)qb * 128 * HD, cntC);
        stage_rows(cV, g_v16 + hb + (size_t)qb * 128 * HD, cntC);
        stage_rows(smb + SBGK,        g_k16 + hb, 16);
        stage_rows(smb + SBGK + 2304, g_v16 + hb, 16);
        CP_COMMIT();

        CP_WAIT2(); __syncthreads();
#pragma unroll
        for (int ks = 0; ks < 4; ks++) ldmx4(qf[ks], qrow + ks * 32);
        dense_block<8, 0>(qf, smb + SBA, smb + SBA + 18432, lane, rblk,
                          ch2 * 64, i0, (qb - 1) * 128 + ch2 * 64, oacc, m, l);
        CP_WAIT0(); __syncthreads();
        dense_block<8, 1>(qf, bK - (uint32_t)cminB * 144, bV - (uint32_t)cminB * 144,
                          lane, rblk, ch2 * 64, i0, (qb - 2) * 128 + ch2 * 64, oacc, m, l);
        dense_block<8, 2>(qf, cK, cV, lane, rblk,
                          ch2 * 64, i0, qb * 128 + ch2 * 64, oacc, m, l);
        if (ch2 == 0)
            dense_block<2, 0>(qf, smb + SBGK, smb + SBGK + 2304, lane, rblk,
                              0, i0, 0, oacc, m, l);
    } else {
        stage_rows(smb + SBA,         g_k16 + hb, 128);
        stage_rows(smb + SBA + 18432, g_v16 + hb, 128);
        CP_COMMIT();
        if (qb >= 1) {
            stage_rows(smb + SLB,         g_k16 + hb + (size_t)128 * HD, 128);
            stage_rows(smb + SLB + 18432, g_v16 + hb + (size_t)128 * HD, 128);
        }
        CP_COMMIT();
        if (qb >= 1) CP_WAIT1(); else CP_WAIT0();
        __syncthreads();
#pragma unroll
        for (int ks = 0; ks < 4; ks++) ldmx4(qf[ks], qrow + ks * 32);
        dense_block<8, 3>(qf, smb + SBA, smb + SBA + 18432, lane, rblk,
                          ch2 * 64, i0, ch2 * 64, oacc, m, l);
        if (qb >= 1) {
            CP_WAIT0();
            __syncthreads();                   // block1 visible; SBA free
            if (qb >= 2) {
                stage_rows(smb + SBA,         g_k16 + hb + (size_t)256 * HD, 128);
                stage_rows(smb + SBA + 18432, g_v16 + hb + (size_t)256 * HD, 128);
                CP_COMMIT();
            }
            dense_block<8, 3>(qf, smb + SLB, smb + SLB + 18432, lane, rblk,
                              ch2 * 64, i0, 128 + ch2 * 64, oacc, m, l);
            if (qb >= 2) {
                CP_WAIT0(); __syncthreads();
                dense_block<8, 3>(qf, smb + SBA, smb + SBA + 18432, lane, rblk,
                                  ch2 * 64, i0, 256 + ch2 * 64, oacc, m, l);
            }
        }
    }

    // ---------- strided diagonals: single-pass, per-warp cp.async pipeline -----
    int nkb = qb - 2;
    if (nkb > 0) {
        __syncthreads();
        uint32_t slab = smb + SLAB + wid * SLABW;
        int part = lane & 3, qr = lane >> 2;

        auto stage_kb = [&](int slot, int kb) {
            size_t rowbase = (size_t)kb * 128 + s * 64 + rg * 16;
            const __half* Ksrc = g_k16 + hb + rowbase * HD;
            const __half* Vsrc = g_v16 + hb + rowbase * HD;
            uint32_t base = slab + slot * 4096;
#pragma unroll
            for (int c = lane; c < 128; c += 32) {
                int row = c >> 3, ch = c & 7;
                cpasync16(base + row * 128 + ch * 16,
                          Ksrc + (size_t)row * HD + ch * 8);
                cpasync16(base + 2048 + row * 128 + ch * 16,
                          Vsrc + (size_t)row * HD + ch * 8);
            }
            CP_COMMIT();
        };

        int nexts = ch2;
#pragma unroll
        for (int st2 = 0; st2 < 3; st2++) {
            if (nexts < nkb) { stage_kb(st2, nexts); nexts += 2; }
        }

        int it = 0;
        for (int kb = ch2; kb < nkb; kb += 2, it++) {
            int ahead = (nexts - kb) >> 1;
            if (ahead >= 3) CP_WAIT2();
            else if (ahead == 2) CP_WAIT1();
            else CP_WAIT0();
            __syncwarp();

            uint32_t st = slab + (it % 3) * 4096;
#pragma unroll
            for (int h = 0; h < 2; h++) {
                int lr = qr + h * 8;
                int rowin128 = s * 64 + rg * 16 + lr;
                float sc;
                if (kb == 0 && rowin128 < 16) {
                    sc = -1e30f;
                } else {
                    uint32_t kaddr = st + lr * 128 + part * 32;
                    uint32_t qaddr = smb + SMQ + (rg * 16 + lr) * 144 + part * 32;
                    float sum = 0.f;
#pragma unroll
                    for (int seg = 0; seg < 2; seg++) {
                        uint32_t k4[4], q4[4];
                        asm volatile("ld.shared.v4.b32 {%0,%1,%2,%3}, [%4];"
                            : "=r"(k4[0]), "=r"(k4[1]), "=r"(k4[2]), "=r"(k4[3])
                            : "r"(kaddr + seg * 16));
                        asm volatile("ld.shared.v4.b32 {%0,%1,%2,%3}, [%4];"
                            : "=r"(q4[0]), "=r"(q4[1]), "=r"(q4[2]), "=r"(q4[3])
                            : "r"(qaddr + seg * 16));
#pragma unroll
                        for (int u = 0; u < 4; u++) {
                            float2 qf2 = h2f2(q4[u]), kf = h2f2(k4[u]);
                            sum += qf2.x * kf.x + qf2.y * kf.y;
                        }
                    }
                    sum += __shfl_xor_sync(0xffffffffu, sum, 1);
                    sum += __shfl_xor_sync(0xffffffffu, sum, 2);
                    sc = sum * SCALE2;
                }
                float mold = m[h];
                float mx = fmaxf(fmaxf(mold, sc), -1e28f);
                float p = ex2(sc - mx);
                if (__any_sync(0xffffffffu, mx > mold)) {
                    float cs = ex2(mold - mx);
                    l[h] = l[h] * cs + p;
                    m[h] = mx;
#pragma unroll
                    for (int nd = 0; nd < 8; nd++) {
                        oacc[nd][h * 2 + 0] *= cs;
                        oacc[nd][h * 2 + 1] *= cs;
                    }
                } else {
                    l[h] += p;
                }
                uint32_t vaddr = st + 2048 + lr * 128 + part * 4;
#pragma unroll
                for (int nd = 0; nd < 8; nd++) {
                    uint32_t vv;
                    asm volatile("ld.shared.b32 %0, [%1];"
                        : "=r"(vv) : "r"(vaddr + nd * 16));
                    float2 vf = h2f2(vv);
                    oacc[nd][h * 2 + 0] += p * vf.x;
                    oacc[nd][h * 2 + 1] += p * vf.y;
                }
            }

            if (nexts < nkb) {
                __syncwarp();
                stage_kb(it % 3, nexts);
                nexts += 2;
            }
        }
    }

    // pairwise split-softmax merge, then epilogue
    __syncthreads();
    {
        char* mb = sm + SMRG + wid * MERGE_B;
#pragma unroll
        for (int h = 0; h < 2; h++) {
            int row = (lane >> 2) + h * 8;
#pragma unroll
            for (int nd = 0; nd < 8; nd++) {
                int col = nd * 8 + (lane & 3) * 2;
                *(float2*)(mb + (row * 64 + col) * 4) =
                    make_float2(oacc[nd][h * 2], oacc[nd][h * 2 + 1]);
            }
            if ((lane & 3) == 0)
                *(float2*)(mb + 4096 + row * 8) = make_float2(m[h], l[h]);
        }
    }
    __syncthreads();
    if (ch2 == 0) {
        char* pb = sm + SMRG + (wid + 1) * MERGE_B;
        int b = bh >> 4, head = bh & 15;
#pragma unroll
        for (int h = 0; h < 2; h++) {
            int row = (lane >> 2) + h * 8;
            float2 ml = *(float2*)(pb + 4096 + row * 8);
            float mx = fmaxf(m[h], ml.x);
            float f0 = ex2(m[h] - mx), f1 = ex2(ml.x - mx);
            float L = l[h] * f0 + ml.y * f1;
            float inv = 1.f / L;
            int i = qt * 64 + rg * 16 + row;
            size_t row_off = ((size_t)(b * TSEQ + i)) * CEMB + head * HD;
#pragma unroll
            for (int nd = 0; nd < 8; nd++) {
                int col = nd * 8 + (lane & 3) * 2;
                float2 o1 = *(float2*)(pb + (row * 64 + col) * 4);
                float y0 = (oacc[nd][h * 2 + 0] * f0 + o1.x * f1) * inv;
                float y1 = (oacc[nd][h * 2 + 1] * f0 + o1.y * f1) * inv;
                *(uint32_t*)&g_y16[row_off + col] = packh(y0, y1);
            }
        }
    }
}

// ---------------- launch -------------------------------------------------------
extern "C" void kernel_launch(void* const* d_in, const int* in_sizes, int n_in,
                              void* d_out, int out_size)
{
    const float* x      = (const float*)d_in[0];
    const float* w_qkv  = (const float*)d_in[1];
    const float* b_qkv  = (const float*)d_in[2];
    const float* w_proj = (const float*)d_in[3];
    const float* b_proj = (const float*)d_in[4];
    float* out = (float*)d_out;

    cudaFuncSetAttribute(gemm_mma<0>,
                         cudaFuncAttributeMaxDynamicSharedMemorySize, GSMEM);
    cudaFuncSetAttribute(gemm_mma<1>,
                         cudaFuncAttributeMaxDynamicSharedMemorySize, GSMEM);
    cudaFuncSetAttribute(attn_mma,
                         cudaFuncAttributeMaxDynamicSharedMemorySize, ATTN_SM);

    conv_all<<<12288, 256>>>(x, w_qkv, w_proj);
    gemm_mma<0><<<dim3(3 * CEMB / 128, MROWS / 128), 256, GSMEM>>>(b_qkv, nullptr);
    attn_mma<<<dim3(TSEQ / 64, BATCH * NH), 256, ATTN_SM>>>();
    gemm_mma<1><<<dim3(CEMB / 128, MROWS / 128), 256, GSMEM>>>(b_proj, out);
}